// round 1
// baseline (speedup 1.0000x reference)
#include <cuda_runtime.h>
#include <math.h>

// DoubleNet: two 4-layer MLPs + per-sample 17x17 Sinkhorn (linear domain, 40 rounds)
// B = 32768, D = 256, H = 128, A = I = 16, EPS = 0.1

#define MAXB 32768

// scratch (static __device__ arrays: allocation-free per harness rules)
__device__ float g_t0[MAXB * 128];
__device__ float g_t1[MAXB * 128];
__device__ float g_mat[MAXB * 256];
__device__ float g_frac[MAXB * 16];

// ---------------------------------------------------------------------------
// GEMM: C = act(A @ W + bias).  A: MxK row-major, W: KxN row-major, bias: N.
// BM=128, BN=128, BK=16, 256 threads, 8x8 per-thread microtile.
// ACT: 0 = identity, 1 = tanh
// ---------------------------------------------------------------------------
template <int ACT>
__global__ void __launch_bounds__(256) gemm_bias_act(
    const float* __restrict__ A, const float* __restrict__ W,
    const float* __restrict__ bias, float* __restrict__ C,
    int M, int N, int K)
{
    __shared__ float As[16][132];  // [k][m], padded
    __shared__ float Bs[16][128];  // [k][n]

    const int bm  = blockIdx.y * 128;
    const int bn  = blockIdx.x * 128;
    const int tid = threadIdx.x;
    const int tx  = tid & 15;   // n-group
    const int ty  = tid >> 4;   // m-group

    float acc[8][8];
#pragma unroll
    for (int i = 0; i < 8; i++)
#pragma unroll
        for (int j = 0; j < 8; j++) acc[i][j] = 0.f;

    for (int k0 = 0; k0 < K; k0 += 16) {
        // Load A tile (128x16) transposed into As
#pragma unroll
        for (int l = 0; l < 2; l++) {
            int idx = l * 256 + tid;
            int m = idx >> 2, kq = idx & 3;
            float4 a4 = ((const float4*)(A + (size_t)(bm + m) * K + k0))[kq];
            As[kq * 4 + 0][m] = a4.x;
            As[kq * 4 + 1][m] = a4.y;
            As[kq * 4 + 2][m] = a4.z;
            As[kq * 4 + 3][m] = a4.w;
        }
        // Load B tile (16x128)
#pragma unroll
        for (int l = 0; l < 2; l++) {
            int idx = l * 256 + tid;
            int k = idx >> 5, nq = idx & 31;
            float4 b4 = ((const float4*)(W + (size_t)(k0 + k) * N + bn))[nq];
            *(float4*)&Bs[k][nq * 4] = b4;
        }
        __syncthreads();

#pragma unroll
        for (int k = 0; k < 16; k++) {
            float a[8], b[8];
            float4 t;
            t = *(const float4*)&As[k][ty * 8];     a[0]=t.x; a[1]=t.y; a[2]=t.z; a[3]=t.w;
            t = *(const float4*)&As[k][ty * 8 + 4]; a[4]=t.x; a[5]=t.y; a[6]=t.z; a[7]=t.w;
            t = *(const float4*)&Bs[k][tx * 8];     b[0]=t.x; b[1]=t.y; b[2]=t.z; b[3]=t.w;
            t = *(const float4*)&Bs[k][tx * 8 + 4]; b[4]=t.x; b[5]=t.y; b[6]=t.z; b[7]=t.w;
#pragma unroll
            for (int i = 0; i < 8; i++)
#pragma unroll
                for (int j = 0; j < 8; j++)
                    acc[i][j] = fmaf(a[i], b[j], acc[i][j]);
        }
        __syncthreads();
    }

    float bv[8];
    {
        float4 t0 = *(const float4*)&bias[bn + tx * 8];
        float4 t1 = *(const float4*)&bias[bn + tx * 8 + 4];
        bv[0]=t0.x; bv[1]=t0.y; bv[2]=t0.z; bv[3]=t0.w;
        bv[4]=t1.x; bv[5]=t1.y; bv[6]=t1.z; bv[7]=t1.w;
    }
#pragma unroll
    for (int i = 0; i < 8; i++) {
        float out[8];
#pragma unroll
        for (int j = 0; j < 8; j++) {
            float x = acc[i][j] + bv[j];
            out[j] = (ACT == 1) ? tanhf(x) : x;
        }
        float* cp = C + (size_t)(bm + ty * 8 + i) * N + bn + tx * 8;
        *(float4*)cp       = make_float4(out[0], out[1], out[2], out[3]);
        *(float4*)(cp + 4) = make_float4(out[4], out[5], out[6], out[7]);
    }
}

// ---------------------------------------------------------------------------
// Payment head: frac = sigmoid(P @ pw3 + pb3).  P: Mx128, W: 128x16.
// Thread t -> (m = t>>4, n = t&15); p[k] broadcasts across the 16-thread group,
// W[k*16+n] coalesced across n. Tiny compute (67 M-MAC total).
// ---------------------------------------------------------------------------
__global__ void pay_head(const float* __restrict__ P, const float* __restrict__ W,
                         const float* __restrict__ b, float* __restrict__ frac, int M)
{
    int t = blockIdx.x * blockDim.x + threadIdx.x;
    if (t >= M * 16) return;
    int n = t & 15;
    const float* p = P + (size_t)(t >> 4) * 128;
    float s = b[n];
#pragma unroll
    for (int k = 0; k < 128; k++) s = fmaf(p[k], W[k * 16 + n], s);
    frac[t] = __fdividef(1.f, 1.f + __expf(-s));
}

// ---------------------------------------------------------------------------
// Sinkhorn (linear domain, exactly equivalent to the reference's log-domain
// iteration): K = exp(mat/eps) interior, border row/col == 1 (not stored).
// u=v=1; each round: u_i = a_i / (K v)_i  then  v_j = b_j / (K^T u)_j,
// with a = b = [1]*16 + [16].  plan = u (.) K (.) v.
// One sample per thread; K in shared SoA sK[idx*32 + lane] (conflict-free).
// 32-thread blocks -> 32 KB static shared, multiple blocks resident per SM.
// ---------------------------------------------------------------------------
__global__ void __launch_bounds__(32) sinkhorn_kernel(
    const float* __restrict__ mat, const float* __restrict__ bids,
    const float* __restrict__ frac, float* __restrict__ outA,
    float* __restrict__ outP)
{
    __shared__ float sK[256 * 32];
    const int tid = threadIdx.x;
    const int s   = blockIdx.x * 32 + tid;
    const float* mrow = mat + (size_t)s * 256;
    float* Kp = sK + tid;

    // Build K = exp(mat * 10) in shared (float4 global reads; L1 absorbs the
    // strided pattern since each lane streams its own contiguous 1KB row).
#pragma unroll 8
    for (int q = 0; q < 64; q++) {
        float4 x = ((const float4*)mrow)[q];
        Kp[(q * 4 + 0) * 32] = __expf(x.x * 10.f);
        Kp[(q * 4 + 1) * 32] = __expf(x.y * 10.f);
        Kp[(q * 4 + 2) * 32] = __expf(x.z * 10.f);
        Kp[(q * 4 + 3) * 32] = __expf(x.w * 10.f);
    }

    float u[17], v[17];
#pragma unroll
    for (int j = 0; j < 17; j++) v[j] = 1.f;

#pragma unroll 1
    for (int rnd = 0; rnd < 40; rnd++) {
        // row pass: r_i = sum_j K_ij v_j  (border col contributes v[16];
        // row 16 is all-ones: r_16 = sum_j v_j)
        float r[17];
#pragma unroll
        for (int i = 0; i < 17; i++) r[i] = v[16];
#pragma unroll
        for (int j = 0; j < 16; j++) {
            float vj = v[j];
            r[16] += vj;
#pragma unroll
            for (int i = 0; i < 16; i++)
                r[i] = fmaf(Kp[(i * 16 + j) * 32], vj, r[i]);
        }
#pragma unroll
        for (int i = 0; i < 16; i++) u[i] = __fdividef(1.f, r[i]);
        u[16] = __fdividef(16.f, r[16]);

        // col pass with updated u
        float c[17];
#pragma unroll
        for (int j = 0; j < 17; j++) c[j] = u[16];
#pragma unroll
        for (int i = 0; i < 16; i++) {
            float ui = u[i];
            c[16] += ui;
#pragma unroll
            for (int j = 0; j < 16; j++)
                c[j] = fmaf(Kp[(i * 16 + j) * 32], ui, c[j]);
        }
#pragma unroll
        for (int j = 0; j < 16; j++) v[j] = __fdividef(1.f, c[j]);
        v[16] = __fdividef(16.f, c[16]);
    }

    // Emit allocs = u_i * K_ij * v_j and payments = frac_i * sum_j allocs*bids
    const float4* brow = (const float4*)(bids + (size_t)s * 256);
    float4* arow = (float4*)(outA + (size_t)s * 256);
    float fr[16];
    {
        const float4* f4 = (const float4*)(frac + (size_t)s * 16);
#pragma unroll
        for (int q = 0; q < 4; q++) {
            float4 t = f4[q];
            fr[q * 4 + 0] = t.x; fr[q * 4 + 1] = t.y;
            fr[q * 4 + 2] = t.z; fr[q * 4 + 3] = t.w;
        }
    }
    float pay[16];
#pragma unroll
    for (int i = 0; i < 16; i++) {
        float ui = u[i];
        float accp = 0.f;
#pragma unroll
        for (int q = 0; q < 4; q++) {
            float4 bb = brow[i * 4 + q];
            float4 av;
            av.x = Kp[(i * 16 + q * 4 + 0) * 32] * ui * v[q * 4 + 0];
            av.y = Kp[(i * 16 + q * 4 + 1) * 32] * ui * v[q * 4 + 1];
            av.z = Kp[(i * 16 + q * 4 + 2) * 32] * ui * v[q * 4 + 2];
            av.w = Kp[(i * 16 + q * 4 + 3) * 32] * ui * v[q * 4 + 3];
            accp += av.x * bb.x + av.y * bb.y + av.z * bb.z + av.w * bb.w;
            arow[i * 4 + q] = av;
        }
        pay[i] = fr[i] * accp;
    }
    float4* prow = (float4*)(outP + (size_t)s * 16);
#pragma unroll
    for (int q = 0; q < 4; q++)
        prow[q] = make_float4(pay[q * 4], pay[q * 4 + 1], pay[q * 4 + 2], pay[q * 4 + 3]);
}

// ---------------------------------------------------------------------------
// Inputs (metadata order):
// 0: bids, 1..8: aw0,ab0,aw1,ab1,aw2,ab2,aw3,ab3, 9..16: pw0,pb0,...,pw3,pb3
// Output: allocs (B*256 floats) then payments (B*16 floats)
// ---------------------------------------------------------------------------
extern "C" void kernel_launch(void* const* d_in, const int* in_sizes, int n_in,
                              void* d_out, int out_size)
{
    const float* bids = (const float*)d_in[0];
    const float* aw0 = (const float*)d_in[1];  const float* ab0 = (const float*)d_in[2];
    const float* aw1 = (const float*)d_in[3];  const float* ab1 = (const float*)d_in[4];
    const float* aw2 = (const float*)d_in[5];  const float* ab2 = (const float*)d_in[6];
    const float* aw3 = (const float*)d_in[7];  const float* ab3 = (const float*)d_in[8];
    const float* pw0 = (const float*)d_in[9];  const float* pb0 = (const float*)d_in[10];
    const float* pw1 = (const float*)d_in[11]; const float* pb1 = (const float*)d_in[12];
    const float* pw2 = (const float*)d_in[13]; const float* pb2 = (const float*)d_in[14];
    const float* pw3 = (const float*)d_in[15]; const float* pb3 = (const float*)d_in[16];

    const int M = in_sizes[0] / 256;  // batch (32768)

    void* p;
    cudaGetSymbolAddress(&p, g_t0);   float* t0  = (float*)p;
    cudaGetSymbolAddress(&p, g_t1);   float* t1  = (float*)p;
    cudaGetSymbolAddress(&p, g_mat);  float* mat = (float*)p;
    cudaGetSymbolAddress(&p, g_frac); float* fr  = (float*)p;

    dim3 blk(256);
    // alloc net: X -> 128 -> 128 -> 128 -> 256 (mat)
    gemm_bias_act<1><<<dim3(1, M / 128), blk>>>(bids, aw0, ab0, t0, M, 128, 256);
    gemm_bias_act<1><<<dim3(1, M / 128), blk>>>(t0,   aw1, ab1, t1, M, 128, 128);
    gemm_bias_act<1><<<dim3(1, M / 128), blk>>>(t1,   aw2, ab2, t0, M, 128, 128);
    gemm_bias_act<0><<<dim3(2, M / 128), blk>>>(t0,   aw3, ab3, mat, M, 256, 128);
    // pay net: X -> 128 -> 128 -> 128 -> 16 (frac)
    gemm_bias_act<1><<<dim3(1, M / 128), blk>>>(bids, pw0, pb0, t0, M, 128, 256);
    gemm_bias_act<1><<<dim3(1, M / 128), blk>>>(t0,   pw1, pb1, t1, M, 128, 128);
    gemm_bias_act<1><<<dim3(1, M / 128), blk>>>(t1,   pw2, pb2, t0, M, 128, 128);
    pay_head<<<(M * 16 + 255) / 256, 256>>>(t0, pw3, pb3, fr, M);

    float* out = (float*)d_out;
    sinkhorn_kernel<<<M / 32, 32>>>(mat, bids, fr, out, out + (size_t)M * 256);
}

// round 3
// speedup vs baseline: 1.2095x; 1.2095x over previous
#include <cuda_runtime.h>
#include <cuda_fp16.h>
#include <cstdint>
#include <math.h>

// DoubleNet on GB300 (plain sm_103 target: no tcgen05 -> use mma.sync HMMA).
// fp16 2-way-split GEMMs (3 products: hi@Whi + hi@Wlo + lo@Whi, fp32 accum)
// + linear-domain Sinkhorn.  B = 32768, D = 256, H = 128, A = I = 16, EPS = 0.1

#define MAXB 32768

// ---------------- scratch (__device__ globals: allocation-free) -------------
__device__ uint32_t g_x [MAXB * 256];   // packed (hi fp16 | lo fp16<<16) input
__device__ uint32_t g_a0[MAXB * 128];   // packed activations ping
__device__ uint32_t g_a1[MAXB * 128];   // packed activations pong
__device__ float    g_mat [MAXB * 256];
__device__ float    g_frac[MAXB * 16];
__device__ uint32_t g_wt[163840];       // packed transposed weights [n][k]

#define OFF_AW0 0
#define OFF_AW1 32768
#define OFF_AW2 49152
#define OFF_AW3 65536
#define OFF_PW0 98304
#define OFF_PW1 131072
#define OFF_PW2 147456

// ---------------- helpers ----------------------------------------------------
__device__ __forceinline__ uint32_t packsplit(float v) {
    __half h = __float2half_rn(v);
    float hf = __half2float(h);
    __half l = __float2half_rn(v - hf);
    return (uint32_t)__half_as_ushort(h) | ((uint32_t)__half_as_ushort(l) << 16);
}

__device__ __forceinline__ void mma16816(float* d, const uint32_t* a, const uint32_t* b) {
    asm volatile(
        "mma.sync.aligned.m16n8k16.row.col.f32.f16.f16.f32 "
        "{%0,%1,%2,%3}, {%4,%5,%6,%7}, {%8,%9}, {%0,%1,%2,%3};"
        : "+f"(d[0]), "+f"(d[1]), "+f"(d[2]), "+f"(d[3])
        : "r"(a[0]), "r"(a[1]), "r"(a[2]), "r"(a[3]), "r"(b[0]), "r"(b[1]));
}

// ---------------- prep kernels ----------------------------------------------
__global__ void pack_x(const float* __restrict__ x, uint32_t* __restrict__ dst, int n) {
    int i = blockIdx.x * 256 + threadIdx.x;
    if (i < n) dst[i] = packsplit(x[i]);
}
// W[K][N] -> dst[n*K + k] packed (transpose to n-major, k contiguous)
__global__ void pack_w(const float* __restrict__ W, uint32_t* __restrict__ dst,
                       int K, int N) {
    int i = blockIdx.x * 256 + threadIdx.x;
    if (i >= K * N) return;
    int n = i / K, k = i - n * K;
    dst[i] = packsplit(W[k * N + n]);
}

// ---------------- SMEM tile layout -------------------------------------------
// Each plane: 128 rows x 128 halves, padded row stride 136 halves (272 B).
// Fragment LDS bank check: bank = (68*row + kpair) mod 32 = 4*row + kpair -> 32 distinct.
#define ROWB 272
#define SM_AHI 0
#define SM_ALO 34816
#define SM_BHI 69632
#define SM_BLO 104448
#define SMEM_BYTES 139264

// loader: packed global tile (128 rows x 128 elems, rowstride_u4 uint4s) ->
// hi/lo half planes in padded SMEM. 256 threads; one warp covers one row (256B).
__device__ __forceinline__ void load_plane_pair(char* hi, char* lo,
                                                const uint4* __restrict__ src,
                                                int rowstride_u4, int tid) {
#pragma unroll
    for (int j = 0; j < 16; j++) {
        int lin = j * 256 + tid;
        int row = lin >> 5;
        int q8  = lin & 31;               // uint4 index within row (4 elems each)
        uint4 v = src[row * rowstride_u4 + q8];
        uint32_t h0 = __byte_perm(v.x, v.y, 0x5410);
        uint32_t h1 = __byte_perm(v.z, v.w, 0x5410);
        uint32_t l0 = __byte_perm(v.x, v.y, 0x7632);
        uint32_t l1 = __byte_perm(v.z, v.w, 0x7632);
        int off = row * ROWB + q8 * 8;
        *(uint2*)(hi + off) = make_uint2(h0, h1);
        *(uint2*)(lo + off) = make_uint2(l0, l1);
    }
}

// ---------------- HMMA GEMM --------------------------------------------------
// D[m][n] = act( sum_k A[m][k] * W[k][n] + bias[n] ), per-CTA tile 128x128.
// A packed [M][KT], Wt packed [nglob][KT].  grid = (NSPLIT, M/128).
// ACT==1: tanh -> packed u32 out (stride 128). ACT==2: identity -> f32 out.
template <int KCHUNKS, int ACT, int OUTSTRIDE>
__global__ void __launch_bounds__(256, 1)
gemm_hmma(const uint32_t* __restrict__ Aact, const uint32_t* __restrict__ Wt,
          const float* __restrict__ bias, void* __restrict__ outp)
{
    constexpr int KT = KCHUNKS * 128;
    extern __shared__ __align__(16) char smem[];

    const int tid  = threadIdx.x;
    const int lane = tid & 31;
    const int w    = tid >> 5;
    const int wm   = (w & 3) * 32;   // warp m-offset (4 warps along M)
    const int wn   = (w >> 2) * 64;  // warp n-offset (2 warps along N)
    const int bm   = blockIdx.y * 128;
    const int noff = blockIdx.x * 128;

    float acc[2][8][4];
#pragma unroll
    for (int i = 0; i < 2; i++)
#pragma unroll
        for (int j = 0; j < 8; j++)
#pragma unroll
            for (int q = 0; q < 4; q++) acc[i][j][q] = 0.f;

    const int r4 = lane >> 2;          // 0..7
    const int kp = (lane & 3) * 4;     // byte offset of k-pair within row

    for (int c = 0; c < KCHUNKS; c++) {
        if (c) __syncthreads();
        load_plane_pair(smem + SM_AHI, smem + SM_ALO,
                        (const uint4*)(Aact + (size_t)bm * KT + c * 128), KT / 4, tid);
        load_plane_pair(smem + SM_BHI, smem + SM_BLO,
                        (const uint4*)(Wt + (size_t)noff * KT + c * 128), KT / 4, tid);
        __syncthreads();

#pragma unroll
        for (int kk = 0; kk < 8; kk++) {
            uint32_t af[2][2][4];  // [plane][mfrag][reg]
#pragma unroll
            for (int p = 0; p < 2; p++) {
                const char* base = smem + (p ? SM_ALO : SM_AHI) + kk * 32 + kp;
#pragma unroll
                for (int i = 0; i < 2; i++) {
                    const char* ab = base + (wm + i * 16 + r4) * ROWB;
                    af[p][i][0] = *(const uint32_t*)ab;
                    af[p][i][1] = *(const uint32_t*)(ab + 8 * ROWB);
                    af[p][i][2] = *(const uint32_t*)(ab + 16);
                    af[p][i][3] = *(const uint32_t*)(ab + 8 * ROWB + 16);
                }
            }
#pragma unroll
            for (int j = 0; j < 8; j++) {
                const char* bh = smem + SM_BHI + (wn + j * 8 + r4) * ROWB + kk * 32 + kp;
                const char* bl = smem + SM_BLO + (wn + j * 8 + r4) * ROWB + kk * 32 + kp;
                uint32_t bhf[2] = { *(const uint32_t*)bh, *(const uint32_t*)(bh + 16) };
                uint32_t blf[2] = { *(const uint32_t*)bl, *(const uint32_t*)(bl + 16) };
#pragma unroll
                for (int i = 0; i < 2; i++) {
                    mma16816(acc[i][j], af[0][i], bhf);
                    mma16816(acc[i][j], af[0][i], blf);
                    mma16816(acc[i][j], af[1][i], bhf);
                }
            }
        }
    }
    __syncthreads();  // all warps done reading SMEM before epilogue reuses it

    // epilogue: bias + act -> SMEM stage (stride 132 words) -> coalesced GMEM
    if (ACT == 1) {
        uint32_t* stage = (uint32_t*)smem;
#pragma unroll
        for (int i = 0; i < 2; i++) {
            int r0 = wm + i * 16 + r4;
#pragma unroll
            for (int j = 0; j < 8; j++) {
                int c0 = wn + j * 8 + (lane & 3) * 2;
                float b0 = bias[c0], b1 = bias[c0 + 1];
                stage[r0 * 132 + c0]           = packsplit(tanhf(acc[i][j][0] + b0));
                stage[r0 * 132 + c0 + 1]       = packsplit(tanhf(acc[i][j][1] + b1));
                stage[(r0 + 8) * 132 + c0]     = packsplit(tanhf(acc[i][j][2] + b0));
                stage[(r0 + 8) * 132 + c0 + 1] = packsplit(tanhf(acc[i][j][3] + b1));
            }
        }
        __syncthreads();
        uint32_t* og = (uint32_t*)outp + (size_t)bm * OUTSTRIDE;
#pragma unroll
        for (int it = 0; it < 64; it++) {
            int lin = it * 256 + tid;
            int row = lin >> 7, col = lin & 127;
            og[row * OUTSTRIDE + col] = stage[row * 132 + col];
        }
    } else {
        float* stage = (float*)smem;
#pragma unroll
        for (int i = 0; i < 2; i++) {
            int r0 = wm + i * 16 + r4;
#pragma unroll
            for (int j = 0; j < 8; j++) {
                int c0 = wn + j * 8 + (lane & 3) * 2;
                float b0 = bias[noff + c0], b1 = bias[noff + c0 + 1];
                stage[r0 * 132 + c0]           = acc[i][j][0] + b0;
                stage[r0 * 132 + c0 + 1]       = acc[i][j][1] + b1;
                stage[(r0 + 8) * 132 + c0]     = acc[i][j][2] + b0;
                stage[(r0 + 8) * 132 + c0 + 1] = acc[i][j][3] + b1;
            }
        }
        __syncthreads();
        float* og = (float*)outp + (size_t)bm * OUTSTRIDE + noff;
#pragma unroll
        for (int it = 0; it < 64; it++) {
            int lin = it * 256 + tid;
            int row = lin >> 7, col = lin & 127;
            og[row * OUTSTRIDE + col] = stage[row * 132 + col];
        }
    }
}

// ---------------- payment head (tiny) ----------------------------------------
__global__ void pay_head(const uint32_t* __restrict__ P, const float* __restrict__ W,
                         const float* __restrict__ b, float* __restrict__ frac, int M)
{
    int t = blockIdx.x * blockDim.x + threadIdx.x;
    if (t >= M * 16) return;
    int n = t & 15;
    const uint32_t* p = P + (size_t)(t >> 4) * 128;
    float s = b[n];
#pragma unroll
    for (int k = 0; k < 128; k++) {
        uint32_t v = p[k];
        float pv = __half2float(__ushort_as_half((unsigned short)(v & 0xFFFF)))
                 + __half2float(__ushort_as_half((unsigned short)(v >> 16)));
        s = fmaf(pv, W[k * 16 + n], s);
    }
    frac[t] = __fdividef(1.f, 1.f + __expf(-s));
}

// ---------------- Sinkhorn (linear domain, proven in R1) ----------------------
__global__ void __launch_bounds__(32) sinkhorn_kernel(
    const float* __restrict__ mat, const float* __restrict__ bids,
    const float* __restrict__ frac, float* __restrict__ outA,
    float* __restrict__ outP)
{
    __shared__ float sK[256 * 32];
    const int tid = threadIdx.x;
    const int s   = blockIdx.x * 32 + tid;
    const float* mrow = mat + (size_t)s * 256;
    float* Kp = sK + tid;

#pragma unroll 8
    for (int q = 0; q < 64; q++) {
        float4 x = ((const float4*)mrow)[q];
        Kp[(q * 4 + 0) * 32] = __expf(x.x * 10.f);
        Kp[(q * 4 + 1) * 32] = __expf(x.y * 10.f);
        Kp[(q * 4 + 2) * 32] = __expf(x.z * 10.f);
        Kp[(q * 4 + 3) * 32] = __expf(x.w * 10.f);
    }

    float u[17], v[17];
#pragma unroll
    for (int j = 0; j < 17; j++) v[j] = 1.f;

#pragma unroll 1
    for (int rnd = 0; rnd < 40; rnd++) {
        float r[17];
#pragma unroll
        for (int i = 0; i < 17; i++) r[i] = v[16];
#pragma unroll
        for (int j = 0; j < 16; j++) {
            float vj = v[j];
            r[16] += vj;
#pragma unroll
            for (int i = 0; i < 16; i++)
                r[i] = fmaf(Kp[(i * 16 + j) * 32], vj, r[i]);
        }
#pragma unroll
        for (int i = 0; i < 16; i++) u[i] = __fdividef(1.f, r[i]);
        u[16] = __fdividef(16.f, r[16]);

        float c[17];
#pragma unroll
        for (int j = 0; j < 17; j++) c[j] = u[16];
#pragma unroll
        for (int i = 0; i < 16; i++) {
            float ui = u[i];
            c[16] += ui;
#pragma unroll
            for (int j = 0; j < 16; j++)
                c[j] = fmaf(Kp[(i * 16 + j) * 32], ui, c[j]);
        }
#pragma unroll
        for (int j = 0; j < 16; j++) v[j] = __fdividef(1.f, c[j]);
        v[16] = __fdividef(16.f, c[16]);
    }

    const float4* brow = (const float4*)(bids + (size_t)s * 256);
    float4* arow = (float4*)(outA + (size_t)s * 256);
    float fr[16];
    {
        const float4* f4 = (const float4*)(frac + (size_t)s * 16);
#pragma unroll
        for (int q = 0; q < 4; q++) {
            float4 t = f4[q];
            fr[q * 4 + 0] = t.x; fr[q * 4 + 1] = t.y;
            fr[q * 4 + 2] = t.z; fr[q * 4 + 3] = t.w;
        }
    }
    float pay[16];
#pragma unroll
    for (int i = 0; i < 16; i++) {
        float ui = u[i];
        float accp = 0.f;
#pragma unroll
        for (int q = 0; q < 4; q++) {
            float4 bb = brow[i * 4 + q];
            float4 av;
            av.x = Kp[(i * 16 + q * 4 + 0) * 32] * ui * v[q * 4 + 0];
            av.y = Kp[(i * 16 + q * 4 + 1) * 32] * ui * v[q * 4 + 1];
            av.z = Kp[(i * 16 + q * 4 + 2) * 32] * ui * v[q * 4 + 2];
            av.w = Kp[(i * 16 + q * 4 + 3) * 32] * ui * v[q * 4 + 3];
            accp += av.x * bb.x + av.y * bb.y + av.z * bb.z + av.w * bb.w;
            arow[i * 4 + q] = av;
        }
        pay[i] = fr[i] * accp;
    }
    float4* prow = (float4*)(outP + (size_t)s * 16);
#pragma unroll
    for (int q = 0; q < 4; q++)
        prow[q] = make_float4(pay[q * 4], pay[q * 4 + 1], pay[q * 4 + 2], pay[q * 4 + 3]);
}

// ---------------- launch -----------------------------------------------------
extern "C" void kernel_launch(void* const* d_in, const int* in_sizes, int n_in,
                              void* d_out, int out_size)
{
    const float* bids = (const float*)d_in[0];
    const float* aw0 = (const float*)d_in[1];  const float* ab0 = (const float*)d_in[2];
    const float* aw1 = (const float*)d_in[3];  const float* ab1 = (const float*)d_in[4];
    const float* aw2 = (const float*)d_in[5];  const float* ab2 = (const float*)d_in[6];
    const float* aw3 = (const float*)d_in[7];  const float* ab3 = (const float*)d_in[8];
    const float* pw0 = (const float*)d_in[9];  const float* pb0 = (const float*)d_in[10];
    const float* pw1 = (const float*)d_in[11]; const float* pb1 = (const float*)d_in[12];
    const float* pw2 = (const float*)d_in[13]; const float* pb2 = (const float*)d_in[14];
    const float* pw3 = (const float*)d_in[15]; const float* pb3 = (const float*)d_in[16];

    const int M = in_sizes[0] / 256;  // 32768

    void* p;
    cudaGetSymbolAddress(&p, g_x);    uint32_t* x  = (uint32_t*)p;
    cudaGetSymbolAddress(&p, g_a0);   uint32_t* a0 = (uint32_t*)p;
    cudaGetSymbolAddress(&p, g_a1);   uint32_t* a1 = (uint32_t*)p;
    cudaGetSymbolAddress(&p, g_mat);  float* mat = (float*)p;
    cudaGetSymbolAddress(&p, g_frac); float* fr  = (float*)p;
    cudaGetSymbolAddress(&p, g_wt);   uint32_t* wt = (uint32_t*)p;

    cudaFuncSetAttribute(gemm_hmma<2, 1, 128>, cudaFuncAttributeMaxDynamicSharedMemorySize, SMEM_BYTES);
    cudaFuncSetAttribute(gemm_hmma<1, 1, 128>, cudaFuncAttributeMaxDynamicSharedMemorySize, SMEM_BYTES);
    cudaFuncSetAttribute(gemm_hmma<1, 2, 256>, cudaFuncAttributeMaxDynamicSharedMemorySize, SMEM_BYTES);

    // prep: pack inputs + transposed split weights
    pack_x<<<(M * 256 + 255) / 256, 256>>>(bids, x, M * 256);
    pack_w<<<128, 256>>>(aw0, wt + OFF_AW0, 256, 128);
    pack_w<<<64,  256>>>(aw1, wt + OFF_AW1, 128, 128);
    pack_w<<<64,  256>>>(aw2, wt + OFF_AW2, 128, 128);
    pack_w<<<128, 256>>>(aw3, wt + OFF_AW3, 128, 256);
    pack_w<<<128, 256>>>(pw0, wt + OFF_PW0, 256, 128);
    pack_w<<<64,  256>>>(pw1, wt + OFF_PW1, 128, 128);
    pack_w<<<64,  256>>>(pw2, wt + OFF_PW2, 128, 128);

    const int G = M / 128;  // 256
    // alloc net: 256 -> 128 -> 128 -> 128 -> 256 (mat)
    gemm_hmma<2, 1, 128><<<dim3(1, G), 256, SMEM_BYTES>>>(x,  wt + OFF_AW0, ab0, a0);
    gemm_hmma<1, 1, 128><<<dim3(1, G), 256, SMEM_BYTES>>>(a0, wt + OFF_AW1, ab1, a1);
    gemm_hmma<1, 1, 128><<<dim3(1, G), 256, SMEM_BYTES>>>(a1, wt + OFF_AW2, ab2, a0);
    gemm_hmma<1, 2, 256><<<dim3(2, G), 256, SMEM_BYTES>>>(a0, wt + OFF_AW3, ab3, mat);
    // pay net: 256 -> 128 -> 128 -> 128 -> 16 (frac)
    gemm_hmma<2, 1, 128><<<dim3(1, G), 256, SMEM_BYTES>>>(x,  wt + OFF_PW0, pb0, a1);
    gemm_hmma<1, 1, 128><<<dim3(1, G), 256, SMEM_BYTES>>>(a1, wt + OFF_PW1, pb1, a0);
    gemm_hmma<1, 1, 128><<<dim3(1, G), 256, SMEM_BYTES>>>(a0, wt + OFF_PW2, pb2, a1);
    pay_head<<<(M * 16 + 255) / 256, 256>>>(a1, pw3, pb3, fr, M);

    float* out = (float*)d_out;
    sinkhorn_kernel<<<M / 32, 32>>>(mat, bids, fr, out, out + (size_t)M * 256);
}

// round 4
// speedup vs baseline: 1.6787x; 1.3880x over previous
#include <cuda_runtime.h>
#include <cuda_fp16.h>
#include <cstdint>
#include <math.h>

// DoubleNet (sm_103, HMMA): fp16 2-way-split GEMMs via ldmatrix + mma.sync,
// f16-accum correction products, z-merged nets, register-resident Sinkhorn.
// B = 32768, D = 256, H = 128, A = I = 16, EPS = 0.1

#define MAXB 32768

__device__ uint32_t g_x [MAXB * 256];   // packed (hi fp16 | lo fp16<<16) input
__device__ uint32_t g_a0[MAXB * 128];   // alloc-net ping
__device__ uint32_t g_a1[MAXB * 128];   // alloc-net pong
__device__ uint32_t g_b0[MAXB * 128];   // pay-net ping
__device__ uint32_t g_b1[MAXB * 128];   // pay-net pong
__device__ float    g_mat [MAXB * 256];
__device__ float    g_frac[MAXB * 16];
__device__ uint32_t g_wt[163840];       // packed transposed weights [n][k]

#define OFF_AW0 0
#define OFF_AW1 32768
#define OFF_AW2 49152
#define OFF_AW3 65536
#define OFF_PW0 98304
#define OFF_PW1 131072
#define OFF_PW2 147456

// ---------------- helpers ----------------------------------------------------
__device__ __forceinline__ uint32_t smem_u32(const void* p) {
    uint32_t a;
    asm("{ .reg .u64 t; cvta.to.shared.u64 t, %1; cvt.u32.u64 %0, t; }"
        : "=r"(a) : "l"(p));
    return a;
}
__device__ __forceinline__ uint32_t packsplit(float v) {
    __half h = __float2half_rn(v);
    float hf = __half2float(h);
    __half l = __float2half_rn(v - hf);
    return (uint32_t)__half_as_ushort(h) | ((uint32_t)__half_as_ushort(l) << 16);
}
__device__ __forceinline__ void mma16816_f(float* d, const uint32_t* a, const uint32_t* b) {
    asm volatile(
        "mma.sync.aligned.m16n8k16.row.col.f32.f16.f16.f32 "
        "{%0,%1,%2,%3}, {%4,%5,%6,%7}, {%8,%9}, {%0,%1,%2,%3};"
        : "+f"(d[0]), "+f"(d[1]), "+f"(d[2]), "+f"(d[3])
        : "r"(a[0]), "r"(a[1]), "r"(a[2]), "r"(a[3]), "r"(b[0]), "r"(b[1]));
}
__device__ __forceinline__ void mma16816_h(uint32_t* d, const uint32_t* a, const uint32_t* b) {
    asm volatile(
        "mma.sync.aligned.m16n8k16.row.col.f16.f16.f16.f16 "
        "{%0,%1}, {%2,%3,%4,%5}, {%6,%7}, {%0,%1};"
        : "+r"(d[0]), "+r"(d[1])
        : "r"(a[0]), "r"(a[1]), "r"(a[2]), "r"(a[3]), "r"(b[0]), "r"(b[1]));
}
#define LDSM4(R, addr) \
    asm volatile("ldmatrix.sync.aligned.m8n8.x4.shared.b16 {%0,%1,%2,%3}, [%4];" \
                 : "=r"((R)[0]), "=r"((R)[1]), "=r"((R)[2]), "=r"((R)[3]) : "r"(addr))

// ---------------- prep kernels ----------------------------------------------
__global__ void pack_x(const float* __restrict__ x, uint32_t* __restrict__ dst, int n) {
    int i = blockIdx.x * 256 + threadIdx.x;
    if (i < n) dst[i] = packsplit(x[i]);
}
// all 7 weights in one launch: W[K][N] -> wt[off + n*K + k] packed
__global__ void pack_w_all(const float* __restrict__ aw0, const float* __restrict__ aw1,
                           const float* __restrict__ aw2, const float* __restrict__ aw3,
                           const float* __restrict__ pw0, const float* __restrict__ pw1,
                           const float* __restrict__ pw2, uint32_t* __restrict__ wt)
{
    const float* src; int K, N, off;
    switch (blockIdx.y) {
        case 0: src = aw0; K = 256; N = 128; off = OFF_AW0; break;
        case 1: src = aw1; K = 128; N = 128; off = OFF_AW1; break;
        case 2: src = aw2; K = 128; N = 128; off = OFF_AW2; break;
        case 3: src = aw3; K = 128; N = 256; off = OFF_AW3; break;
        case 4: src = pw0; K = 256; N = 128; off = OFF_PW0; break;
        case 5: src = pw1; K = 128; N = 128; off = OFF_PW1; break;
        default: src = pw2; K = 128; N = 128; off = OFF_PW2; break;
    }
    int i = blockIdx.x * 256 + threadIdx.x;
    if (i >= K * N) return;
    int n = i / K, k = i - n * K;
    wt[off + i] = packsplit(src[k * N + n]);
}

// ---------------- SMEM tile layout -------------------------------------------
// Plane: 128 rows x 128 halves, row stride 272 B (=17*16B: ldmatrix conflict-free).
#define ROWB  272
#define PLANE 34816
#define SM_AHI 0
#define SM_ALO 34816
#define SM_BHI 69632
#define SM_BLO 104448
#define SMEM_BYTES 139264

__device__ __forceinline__ void load_plane_pair(char* hi, char* lo,
                                                const uint4* __restrict__ src,
                                                int rowstride_u4, int tid) {
#pragma unroll
    for (int j = 0; j < 16; j++) {
        int lin = j * 256 + tid;
        int row = lin >> 5;
        int q8  = lin & 31;
        uint4 v = src[row * rowstride_u4 + q8];
        uint32_t h0 = __byte_perm(v.x, v.y, 0x5410);
        uint32_t h1 = __byte_perm(v.z, v.w, 0x5410);
        uint32_t l0 = __byte_perm(v.x, v.y, 0x7632);
        uint32_t l1 = __byte_perm(v.z, v.w, 0x7632);
        int off = row * ROWB + q8 * 8;
        *(uint2*)(hi + off) = make_uint2(h0, h1);
        *(uint2*)(lo + off) = make_uint2(l0, l1);
    }
}

// ---------------- HMMA GEMM --------------------------------------------------
// blockIdx.z selects net (0/1). Tile 128x128, 8 warps (4 M x 2 N), warp 32x64.
// hi@Whi in f32 accum; (hi@Wlo + lo@Whi) in f16 accum, merged at the end.
template <int KCHUNKS, int ACT, int OUTSTRIDE>
__global__ void __launch_bounds__(256, 1)
gemm_hmma(const uint32_t* __restrict__ A0, const uint32_t* __restrict__ A1,
          const uint32_t* __restrict__ W0, const uint32_t* __restrict__ W1,
          const float* __restrict__ bias0, const float* __restrict__ bias1,
          void* __restrict__ out0, void* __restrict__ out1)
{
    constexpr int KT = KCHUNKS * 128;
    extern __shared__ __align__(16) char smem[];

    const uint32_t* Aact = blockIdx.z ? A1 : A0;
    const uint32_t* Wt   = blockIdx.z ? W1 : W0;
    const float* bias    = blockIdx.z ? bias1 : bias0;
    void* outp           = blockIdx.z ? out1 : out0;

    const int tid  = threadIdx.x;
    const int lane = tid & 31;
    const int w    = tid >> 5;
    const int wm   = (w & 3) * 32;
    const int wn   = (w >> 2) * 64;
    const int bm   = blockIdx.y * 128;
    const int noff = blockIdx.x * 128;

    float acc[2][8][4];
    uint32_t acc16[2][8][2];
#pragma unroll
    for (int i = 0; i < 2; i++)
#pragma unroll
        for (int j = 0; j < 8; j++) {
#pragma unroll
            for (int q = 0; q < 4; q++) acc[i][j][q] = 0.f;
            acc16[i][j][0] = 0u; acc16[i][j][1] = 0u;
        }

    const uint32_t sb = smem_u32(smem);
    const int l15 = lane & 15;
    const int lhi = (lane >> 4) * 16;
    const uint32_t aBase = sb + SM_AHI + (uint32_t)(wm + l15) * ROWB + lhi;
    const uint32_t bBase = sb + SM_BHI + (uint32_t)(wn + l15) * ROWB + lhi;

    for (int c = 0; c < KCHUNKS; c++) {
        if (c) __syncthreads();
        load_plane_pair(smem + SM_AHI, smem + SM_ALO,
                        (const uint4*)(Aact + (size_t)bm * KT + c * 128), KT / 4, tid);
        load_plane_pair(smem + SM_BHI, smem + SM_BLO,
                        (const uint4*)(Wt + (size_t)noff * KT + c * 128), KT / 4, tid);
        __syncthreads();

#pragma unroll
        for (int kk = 0; kk < 8; kk++) {
            uint32_t ahi[2][4], alo[2][4];
#pragma unroll
            for (int i = 0; i < 2; i++) {
                LDSM4(ahi[i], aBase + i * (16 * ROWB) + kk * 32);
                LDSM4(alo[i], aBase + PLANE + i * (16 * ROWB) + kk * 32);
            }
            uint32_t bhi[8][2], blo[8][2];
#pragma unroll
            for (int jj = 0; jj < 4; jj++) {
                uint32_t r[4];
                LDSM4(r, bBase + jj * (16 * ROWB) + kk * 32);
                bhi[2 * jj][0] = r[0]; bhi[2 * jj + 1][0] = r[1];
                bhi[2 * jj][1] = r[2]; bhi[2 * jj + 1][1] = r[3];
                LDSM4(r, bBase + PLANE + jj * (16 * ROWB) + kk * 32);
                blo[2 * jj][0] = r[0]; blo[2 * jj + 1][0] = r[1];
                blo[2 * jj][1] = r[2]; blo[2 * jj + 1][1] = r[3];
            }
#pragma unroll
            for (int j = 0; j < 8; j++)
#pragma unroll
                for (int i = 0; i < 2; i++) {
                    mma16816_f(acc[i][j], ahi[i], bhi[j]);
                    mma16816_h(acc16[i][j], ahi[i], blo[j]);
                    mma16816_h(acc16[i][j], alo[i], bhi[j]);
                }
        }
    }

    // merge f16 correction accumulators into f32
#pragma unroll
    for (int i = 0; i < 2; i++)
#pragma unroll
        for (int j = 0; j < 8; j++) {
            float2 f0 = __half22float2(*reinterpret_cast<__half2*>(&acc16[i][j][0]));
            float2 f1 = __half22float2(*reinterpret_cast<__half2*>(&acc16[i][j][1]));
            acc[i][j][0] += f0.x; acc[i][j][1] += f0.y;
            acc[i][j][2] += f1.x; acc[i][j][3] += f1.y;
        }

    __syncthreads();

    const int r4 = lane >> 2;
    if (ACT == 1) {
        uint32_t* stage = (uint32_t*)smem;
#pragma unroll
        for (int i = 0; i < 2; i++) {
            int r0 = wm + i * 16 + r4;
#pragma unroll
            for (int j = 0; j < 8; j++) {
                int c0 = wn + j * 8 + (lane & 3) * 2;
                float b0 = bias[c0], b1 = bias[c0 + 1];
                stage[r0 * 132 + c0]           = packsplit(tanhf(acc[i][j][0] + b0));
                stage[r0 * 132 + c0 + 1]       = packsplit(tanhf(acc[i][j][1] + b1));
                stage[(r0 + 8) * 132 + c0]     = packsplit(tanhf(acc[i][j][2] + b0));
                stage[(r0 + 8) * 132 + c0 + 1] = packsplit(tanhf(acc[i][j][3] + b1));
            }
        }
        __syncthreads();
        uint32_t* og = (uint32_t*)outp + (size_t)bm * OUTSTRIDE;
#pragma unroll
        for (int it = 0; it < 64; it++) {
            int lin = it * 256 + tid;
            int row = lin >> 7, col = lin & 127;
            og[row * OUTSTRIDE + col] = stage[row * 132 + col];
        }
    } else {
        float* stage = (float*)smem;
#pragma unroll
        for (int i = 0; i < 2; i++) {
            int r0 = wm + i * 16 + r4;
#pragma unroll
            for (int j = 0; j < 8; j++) {
                int c0 = wn + j * 8 + (lane & 3) * 2;
                float b0 = bias[noff + c0], b1 = bias[noff + c0 + 1];
                stage[r0 * 132 + c0]           = acc[i][j][0] + b0;
                stage[r0 * 132 + c0 + 1]       = acc[i][j][1] + b1;
                stage[(r0 + 8) * 132 + c0]     = acc[i][j][2] + b0;
                stage[(r0 + 8) * 132 + c0 + 1] = acc[i][j][3] + b1;
            }
        }
        __syncthreads();
        float* og = (float*)outp + (size_t)bm * OUTSTRIDE + noff;
#pragma unroll
        for (int it = 0; it < 64; it++) {
            int lin = it * 256 + tid;
            int row = lin >> 7, col = lin & 127;
            og[row * OUTSTRIDE + col] = stage[row * 132 + col];
        }
    }
}

// ---------------- payment head (tiny) ----------------------------------------
__global__ void pay_head(const uint32_t* __restrict__ P, const float* __restrict__ W,
                         const float* __restrict__ b, float* __restrict__ frac, int M)
{
    int t = blockIdx.x * blockDim.x + threadIdx.x;
    if (t >= M * 16) return;
    int n = t & 15;
    const uint32_t* p = P + (size_t)(t >> 4) * 128;
    float s = b[n];
#pragma unroll
    for (int k = 0; k < 128; k++) {
        uint32_t v = p[k];
        float pv = __half2float(__ushort_as_half((unsigned short)(v & 0xFFFF)))
                 + __half2float(__ushort_as_half((unsigned short)(v >> 16)));
        s = fmaf(pv, W[k * 16 + n], s);
    }
    frac[t] = __fdividef(1.f, 1.f + __expf(-s));
}

// ---------------- Sinkhorn: register-resident, 2 threads/sample --------------
// Thread parity p owns columns j in [8p, 8p+8): K[16][8] lives in registers.
// Row pass: local partials + shfl.bfly(1) combine. Col pass: fully local.
// Linear-domain iteration identical to R1's (validated rel_err 3.6e-7).
__global__ void __launch_bounds__(256) sinkhorn_reg(
    const float* __restrict__ mat, const float* __restrict__ bids,
    const float* __restrict__ frac, float* __restrict__ outA,
    float* __restrict__ outP)
{
    const int tid = threadIdx.x;
    const int p   = tid & 1;
    const int s   = blockIdx.x * 128 + (tid >> 1);
    const float* mrow = mat + (size_t)s * 256 + p * 8;

    float K[16][8];
#pragma unroll
    for (int i = 0; i < 16; i++) {
        float4 x0 = *(const float4*)(mrow + i * 16);
        float4 x1 = *(const float4*)(mrow + i * 16 + 4);
        K[i][0] = __expf(x0.x * 10.f); K[i][1] = __expf(x0.y * 10.f);
        K[i][2] = __expf(x0.z * 10.f); K[i][3] = __expf(x0.w * 10.f);
        K[i][4] = __expf(x1.x * 10.f); K[i][5] = __expf(x1.y * 10.f);
        K[i][6] = __expf(x1.z * 10.f); K[i][7] = __expf(x1.w * 10.f);
    }

    float v[8], v16 = 1.f;
#pragma unroll
    for (int j = 0; j < 8; j++) v[j] = 1.f;
    float u[16], u16;

#pragma unroll 1
    for (int rnd = 0; rnd < 40; rnd++) {
        // row pass: local partials over own 8 columns
        float r[17];
#pragma unroll
        for (int i = 0; i < 16; i++) {
            float a = K[i][0] * v[0];
#pragma unroll
            for (int j = 1; j < 8; j++) a = fmaf(K[i][j], v[j], a);
            r[i] = a;
        }
        {
            float a = v[0];
#pragma unroll
            for (int j = 1; j < 8; j++) a += v[j];
            r[16] = a;
        }
#pragma unroll
        for (int i = 0; i < 17; i++)
            r[i] += __shfl_xor_sync(0xFFFFFFFFu, r[i], 1);
#pragma unroll
        for (int i = 0; i < 16; i++) u[i] = __fdividef(1.f, r[i] + v16);
        u16 = __fdividef(16.f, r[16] + v16);

        // col pass: fully local (thread owns all rows of its columns)
        float usum = u[0];
#pragma unroll
        for (int i = 1; i < 16; i++) usum += u[i];
#pragma unroll
        for (int j = 0; j < 8; j++) {
            float c = u16;
#pragma unroll
            for (int i = 0; i < 16; i++) c = fmaf(K[i][j], u[i], c);
            v[j] = __fdividef(1.f, c);
        }
        v16 = __fdividef(16.f, usum + u16);
    }

    // epilogue: allocs (own columns) + fused payments
    const float* brow = bids + (size_t)s * 256 + p * 8;
    float* arow = outA + (size_t)s * 256 + p * 8;
    float pp[16];
#pragma unroll
    for (int i = 0; i < 16; i++) {
        float4 b0 = *(const float4*)(brow + i * 16);
        float4 b1 = *(const float4*)(brow + i * 16 + 4);
        float ui = u[i];
        float a0 = ui * K[i][0] * v[0], a1 = ui * K[i][1] * v[1];
        float a2 = ui * K[i][2] * v[2], a3 = ui * K[i][3] * v[3];
        float a4 = ui * K[i][4] * v[4], a5 = ui * K[i][5] * v[5];
        float a6 = ui * K[i][6] * v[6], a7 = ui * K[i][7] * v[7];
        *(float4*)(arow + i * 16)     = make_float4(a0, a1, a2, a3);
        *(float4*)(arow + i * 16 + 4) = make_float4(a4, a5, a6, a7);
        pp[i] = a0 * b0.x + a1 * b0.y + a2 * b0.z + a3 * b0.w
              + a4 * b1.x + a5 * b1.y + a6 * b1.z + a7 * b1.w;
    }
#pragma unroll
    for (int i = 0; i < 16; i++)
        pp[i] += __shfl_xor_sync(0xFFFFFFFFu, pp[i], 1);

    const float* frow = frac + (size_t)s * 16 + p * 8;
    float4 f0 = *(const float4*)frow;
    float4 f1 = *(const float4*)(frow + 4);
    float pay[8];
#pragma unroll
    for (int q = 0; q < 8; q++) pay[q] = p ? pp[8 + q] : pp[q];
    pay[0] *= f0.x; pay[1] *= f0.y; pay[2] *= f0.z; pay[3] *= f0.w;
    pay[4] *= f1.x; pay[5] *= f1.y; pay[6] *= f1.z; pay[7] *= f1.w;
    float* prow = outP + (size_t)s * 16 + p * 8;
    *(float4*)prow       = make_float4(pay[0], pay[1], pay[2], pay[3]);
    *(float4*)(prow + 4) = make_float4(pay[4], pay[5], pay[6], pay[7]);
}

// ---------------- launch -----------------------------------------------------
extern "C" void kernel_launch(void* const* d_in, const int* in_sizes, int n_in,
                              void* d_out, int out_size)
{
    const float* bids = (const float*)d_in[0];
    const float* aw0 = (const float*)d_in[1];  const float* ab0 = (const float*)d_in[2];
    const float* aw1 = (const float*)d_in[3];  const float* ab1 = (const float*)d_in[4];
    const float* aw2 = (const float*)d_in[5];  const float* ab2 = (const float*)d_in[6];
    const float* aw3 = (const float*)d_in[7];  const float* ab3 = (const float*)d_in[8];
    const float* pw0 = (const float*)d_in[9];  const float* pb0 = (const float*)d_in[10];
    const float* pw1 = (const float*)d_in[11]; const float* pb1 = (const float*)d_in[12];
    const float* pw2 = (const float*)d_in[13]; const float* pb2 = (const float*)d_in[14];
    const float* pw3 = (const float*)d_in[15]; const float* pb3 = (const float*)d_in[16];

    const int M = in_sizes[0] / 256;  // 32768

    void* p;
    cudaGetSymbolAddress(&p, g_x);    uint32_t* x  = (uint32_t*)p;
    cudaGetSymbolAddress(&p, g_a0);   uint32_t* a0 = (uint32_t*)p;
    cudaGetSymbolAddress(&p, g_a1);   uint32_t* a1 = (uint32_t*)p;
    cudaGetSymbolAddress(&p, g_b0);   uint32_t* b0 = (uint32_t*)p;
    cudaGetSymbolAddress(&p, g_b1);   uint32_t* b1 = (uint32_t*)p;
    cudaGetSymbolAddress(&p, g_mat);  float* mat = (float*)p;
    cudaGetSymbolAddress(&p, g_frac); float* fr  = (float*)p;
    cudaGetSymbolAddress(&p, g_wt);   uint32_t* wt = (uint32_t*)p;

    cudaFuncSetAttribute(gemm_hmma<2, 1, 128>, cudaFuncAttributeMaxDynamicSharedMemorySize, SMEM_BYTES);
    cudaFuncSetAttribute(gemm_hmma<1, 1, 128>, cudaFuncAttributeMaxDynamicSharedMemorySize, SMEM_BYTES);
    cudaFuncSetAttribute(gemm_hmma<1, 2, 256>, cudaFuncAttributeMaxDynamicSharedMemorySize, SMEM_BYTES);

    pack_x<<<(M * 256 + 255) / 256, 256>>>(bids, x, M * 256);
    pack_w_all<<<dim3(128, 7), 256>>>(aw0, aw1, aw2, aw3, pw0, pw1, pw2, wt);

    const int G = M / 128;  // 256
    // L1..L3: both nets merged via blockIdx.z
    gemm_hmma<2, 1, 128><<<dim3(1, G, 2), 256, SMEM_BYTES>>>(
        x, x, wt + OFF_AW0, wt + OFF_PW0, ab0, pb0, a0, b0);
    gemm_hmma<1, 1, 128><<<dim3(1, G, 2), 256, SMEM_BYTES>>>(
        a0, b0, wt + OFF_AW1, wt + OFF_PW1, ab1, pb1, a1, b1);
    gemm_hmma<1, 1, 128><<<dim3(1, G, 2), 256, SMEM_BYTES>>>(
        a1, b1, wt + OFF_AW2, wt + OFF_PW2, ab2, pb2, a0, b0);
    // L4: mat = a0 @ aw3 + ab3 (identity, N=256)
    gemm_hmma<1, 2, 256><<<dim3(2, G, 1), 256, SMEM_BYTES>>>(
        a0, a0, wt + OFF_AW3, wt + OFF_AW3, ab3, ab3, mat, mat);
    pay_head<<<(M * 16 + 255) / 256, 256>>>(b0, pw3, pb3, fr, M);

    float* out = (float*)d_out;
    sinkhorn_reg<<<M / 128, 256>>>(mat, bids, fr, out, out + (size_t)M * 256);
}

// round 5
// speedup vs baseline: 1.8456x; 1.0995x over previous
#include <cuda_runtime.h>
#include <cuda_fp16.h>
#include <cstdint>
#include <math.h>

// DoubleNet (sm_103, HMMA): fp16 2-way-split GEMMs, 64x128 CTA tiles for
// 2-CTA/SM residency, register-resident Sinkhorn.
// B = 32768, D = 256, H = 128, A = I = 16, EPS = 0.1

#define MAXB 32768

__device__ uint32_t g_x [MAXB * 256];
__device__ uint32_t g_a0[MAXB * 128];
__device__ uint32_t g_a1[MAXB * 128];
__device__ uint32_t g_b0[MAXB * 128];
__device__ uint32_t g_b1[MAXB * 128];
__device__ float    g_mat [MAXB * 256];
__device__ float    g_frac[MAXB * 16];
__device__ uint32_t g_wt[163840];

#define OFF_AW0 0
#define OFF_AW1 32768
#define OFF_AW2 49152
#define OFF_AW3 65536
#define OFF_PW0 98304
#define OFF_PW1 131072
#define OFF_PW2 147456

// ---------------- helpers ----------------------------------------------------
__device__ __forceinline__ uint32_t smem_u32(const void* p) {
    uint32_t a;
    asm("{ .reg .u64 t; cvta.to.shared.u64 t, %1; cvt.u32.u64 %0, t; }"
        : "=r"(a) : "l"(p));
    return a;
}
__device__ __forceinline__ uint32_t packsplit(float v) {
    __half h = __float2half_rn(v);
    float hf = __half2float(h);
    __half l = __float2half_rn(v - hf);
    return (uint32_t)__half_as_ushort(h) | ((uint32_t)__half_as_ushort(l) << 16);
}
__device__ __forceinline__ void mma16816_f(float* d, const uint32_t* a, const uint32_t* b) {
    asm volatile(
        "mma.sync.aligned.m16n8k16.row.col.f32.f16.f16.f32 "
        "{%0,%1,%2,%3}, {%4,%5,%6,%7}, {%8,%9}, {%0,%1,%2,%3};"
        : "+f"(d[0]), "+f"(d[1]), "+f"(d[2]), "+f"(d[3])
        : "r"(a[0]), "r"(a[1]), "r"(a[2]), "r"(a[3]), "r"(b[0]), "r"(b[1]));
}
__device__ __forceinline__ void mma16816_h(uint32_t* d, const uint32_t* a, const uint32_t* b) {
    asm volatile(
        "mma.sync.aligned.m16n8k16.row.col.f16.f16.f16.f16 "
        "{%0,%1}, {%2,%3,%4,%5}, {%6,%7}, {%0,%1};"
        : "+r"(d[0]), "+r"(d[1])
        : "r"(a[0]), "r"(a[1]), "r"(a[2]), "r"(a[3]), "r"(b[0]), "r"(b[1]));
}
#define LDSM4(R, addr) \
    asm volatile("ldmatrix.sync.aligned.m8n8.x4.shared.b16 {%0,%1,%2,%3}, [%4];" \
                 : "=r"((R)[0]), "=r"((R)[1]), "=r"((R)[2]), "=r"((R)[3]) : "r"(addr))

// ---------------- prep kernels ----------------------------------------------
__global__ void pack_x(const float* __restrict__ x, uint32_t* __restrict__ dst, int n) {
    int i = blockIdx.x * 256 + threadIdx.x;
    if (i < n) dst[i] = packsplit(x[i]);
}
__global__ void pack_w_all(const float* __restrict__ aw0, const float* __restrict__ aw1,
                           const float* __restrict__ aw2, const float* __restrict__ aw3,
                           const float* __restrict__ pw0, const float* __restrict__ pw1,
                           const float* __restrict__ pw2, uint32_t* __restrict__ wt)
{
    const float* src; int K, N, off;
    switch (blockIdx.y) {
        case 0: src = aw0; K = 256; N = 128; off = OFF_AW0; break;
        case 1: src = aw1; K = 128; N = 128; off = OFF_AW1; break;
        case 2: src = aw2; K = 128; N = 128; off = OFF_AW2; break;
        case 3: src = aw3; K = 128; N = 256; off = OFF_AW3; break;
        case 4: src = pw0; K = 256; N = 128; off = OFF_PW0; break;
        case 5: src = pw1; K = 128; N = 128; off = OFF_PW1; break;
        default: src = pw2; K = 128; N = 128; off = OFF_PW2; break;
    }
    int i = blockIdx.x * 256 + threadIdx.x;
    if (i >= K * N) return;
    int n = i / K, k = i - n * K;
    wt[off + i] = packsplit(src[k * N + n]);
}

// ---------------- SMEM tile layout -------------------------------------------
// Plane row stride 272 B (=17*16B: ldmatrix conflict-free).
// A: 64 rows (hi, lo planes). B: 128 rows (hi, lo planes).
#define ROWB   272
#define APLANE 17408
#define BPLANE 34816
#define SM_AHI 0
#define SM_ALO 17408
#define SM_BHI 34816
#define SM_BLO 69632
#define SMEM_BYTES 104448

// rows*32 uint4s total; 256 threads.
template <int ROWS>
__device__ __forceinline__ void load_plane_pair(char* hi, char* lo,
                                                const uint4* __restrict__ src,
                                                int rowstride_u4, int tid) {
#pragma unroll
    for (int j = 0; j < ROWS / 8; j++) {
        int lin = j * 256 + tid;
        int row = lin >> 5;
        int q8  = lin & 31;
        uint4 v = src[row * rowstride_u4 + q8];
        uint32_t h0 = __byte_perm(v.x, v.y, 0x5410);
        uint32_t h1 = __byte_perm(v.z, v.w, 0x5410);
        uint32_t l0 = __byte_perm(v.x, v.y, 0x7632);
        uint32_t l1 = __byte_perm(v.z, v.w, 0x7632);
        int off = row * ROWB + q8 * 8;
        *(uint2*)(hi + off) = make_uint2(h0, h1);
        *(uint2*)(lo + off) = make_uint2(l0, l1);
    }
}

// ---------------- HMMA GEMM --------------------------------------------------
// CTA tile 64(M) x 128(N); 8 warps (2M x 4N), warp 32x32.
// hi@Whi f32 accum; (hi@Wlo + lo@Whi) f16 accum, merged at end.
template <int KCHUNKS, int ACT, int OUTSTRIDE>
__global__ void __launch_bounds__(256, 2)
gemm_hmma(const uint32_t* __restrict__ A0, const uint32_t* __restrict__ A1,
          const uint32_t* __restrict__ W0, const uint32_t* __restrict__ W1,
          const float* __restrict__ bias0, const float* __restrict__ bias1,
          void* __restrict__ out0, void* __restrict__ out1)
{
    constexpr int KT = KCHUNKS * 128;
    extern __shared__ __align__(16) char smem[];

    const uint32_t* Aact = blockIdx.z ? A1 : A0;
    const uint32_t* Wt   = blockIdx.z ? W1 : W0;
    const float* bias    = blockIdx.z ? bias1 : bias0;
    void* outp           = blockIdx.z ? out1 : out0;

    const int tid  = threadIdx.x;
    const int lane = tid & 31;
    const int w    = tid >> 5;
    const int wm   = (w & 1) * 32;    // 2 warps along M
    const int wn   = (w >> 1) * 32;   // 4 warps along N
    const int bm   = blockIdx.y * 64;
    const int noff = blockIdx.x * 128;

    float acc[2][4][4];
    uint32_t acc16[2][4][2];
#pragma unroll
    for (int i = 0; i < 2; i++)
#pragma unroll
        for (int j = 0; j < 4; j++) {
#pragma unroll
            for (int q = 0; q < 4; q++) acc[i][j][q] = 0.f;
            acc16[i][j][0] = 0u; acc16[i][j][1] = 0u;
        }

    const uint32_t sb = smem_u32(smem);
    const int l15 = lane & 15;
    const int lhi = (lane >> 4) * 16;
    const uint32_t aBase = sb + SM_AHI + (uint32_t)(wm + l15) * ROWB + lhi;
    const uint32_t bBase = sb + SM_BHI + (uint32_t)(wn + l15) * ROWB + lhi;

    for (int c = 0; c < KCHUNKS; c++) {
        if (c) __syncthreads();
        load_plane_pair<64>(smem + SM_AHI, smem + SM_ALO,
                            (const uint4*)(Aact + (size_t)bm * KT + c * 128), KT / 4, tid);
        load_plane_pair<128>(smem + SM_BHI, smem + SM_BLO,
                             (const uint4*)(Wt + (size_t)noff * KT + c * 128), KT / 4, tid);
        __syncthreads();

#pragma unroll
        for (int kk = 0; kk < 8; kk++) {
            uint32_t ahi[2][4], alo[2][4];
#pragma unroll
            for (int i = 0; i < 2; i++) {
                LDSM4(ahi[i], aBase + i * (16 * ROWB) + kk * 32);
                LDSM4(alo[i], aBase + APLANE + i * (16 * ROWB) + kk * 32);
            }
            uint32_t bhi[4][2], blo[4][2];
#pragma unroll
            for (int jj = 0; jj < 2; jj++) {
                uint32_t r[4];
                LDSM4(r, bBase + jj * (16 * ROWB) + kk * 32);
                bhi[2 * jj][0] = r[0]; bhi[2 * jj + 1][0] = r[1];
                bhi[2 * jj][1] = r[2]; bhi[2 * jj + 1][1] = r[3];
                LDSM4(r, bBase + BPLANE + jj * (16 * ROWB) + kk * 32);
                blo[2 * jj][0] = r[0]; blo[2 * jj + 1][0] = r[1];
                blo[2 * jj][1] = r[2]; blo[2 * jj + 1][1] = r[3];
            }
#pragma unroll
            for (int j = 0; j < 4; j++)
#pragma unroll
                for (int i = 0; i < 2; i++) {
                    mma16816_f(acc[i][j], ahi[i], bhi[j]);
                    mma16816_h(acc16[i][j], ahi[i], blo[j]);
                    mma16816_h(acc16[i][j], alo[i], bhi[j]);
                }
        }
    }

#pragma unroll
    for (int i = 0; i < 2; i++)
#pragma unroll
        for (int j = 0; j < 4; j++) {
            float2 f0 = __half22float2(*reinterpret_cast<__half2*>(&acc16[i][j][0]));
            float2 f1 = __half22float2(*reinterpret_cast<__half2*>(&acc16[i][j][1]));
            acc[i][j][0] += f0.x; acc[i][j][1] += f0.y;
            acc[i][j][2] += f1.x; acc[i][j][3] += f1.y;
        }

    __syncthreads();

    const int r4 = lane >> 2;
    if (ACT == 1) {
        uint32_t* stage = (uint32_t*)smem;
#pragma unroll
        for (int i = 0; i < 2; i++) {
            int r0 = wm + i * 16 + r4;
#pragma unroll
            for (int j = 0; j < 4; j++) {
                int c0 = wn + j * 8 + (lane & 3) * 2;
                float b0 = bias[c0], b1 = bias[c0 + 1];
                stage[r0 * 132 + c0]           = packsplit(tanhf(acc[i][j][0] + b0));
                stage[r0 * 132 + c0 + 1]       = packsplit(tanhf(acc[i][j][1] + b1));
                stage[(r0 + 8) * 132 + c0]     = packsplit(tanhf(acc[i][j][2] + b0));
                stage[(r0 + 8) * 132 + c0 + 1] = packsplit(tanhf(acc[i][j][3] + b1));
            }
        }
        __syncthreads();
        uint32_t* og = (uint32_t*)outp + (size_t)bm * OUTSTRIDE;
#pragma unroll
        for (int it = 0; it < 32; it++) {
            int lin = it * 256 + tid;
            int row = lin >> 7, col = lin & 127;
            og[row * OUTSTRIDE + col] = stage[row * 132 + col];
        }
    } else {
        float* stage = (float*)smem;
#pragma unroll
        for (int i = 0; i < 2; i++) {
            int r0 = wm + i * 16 + r4;
#pragma unroll
            for (int j = 0; j < 4; j++) {
                int c0 = wn + j * 8 + (lane & 3) * 2;
                float b0 = bias[noff + c0], b1 = bias[noff + c0 + 1];
                stage[r0 * 132 + c0]           = acc[i][j][0] + b0;
                stage[r0 * 132 + c0 + 1]       = acc[i][j][1] + b1;
                stage[(r0 + 8) * 132 + c0]     = acc[i][j][2] + b0;
                stage[(r0 + 8) * 132 + c0 + 1] = acc[i][j][3] + b1;
            }
        }
        __syncthreads();
        float* og = (float*)outp + (size_t)bm * OUTSTRIDE + noff;
#pragma unroll
        for (int it = 0; it < 32; it++) {
            int lin = it * 256 + tid;
            int row = lin >> 7, col = lin & 127;
            og[row * OUTSTRIDE + col] = stage[row * 132 + col];
        }
    }
}

// ---------------- payment head -----------------------------------------------
__global__ void pay_head(const uint32_t* __restrict__ P, const float* __restrict__ W,
                         const float* __restrict__ b, float* __restrict__ frac, int M)
{
    int t = blockIdx.x * blockDim.x + threadIdx.x;
    if (t >= M * 16) return;
    int n = t & 15;
    const uint32_t* p = P + (size_t)(t >> 4) * 128;
    float s = b[n];
#pragma unroll
    for (int k = 0; k < 128; k++) {
        uint32_t v = p[k];
        float pv = __half2float(__ushort_as_half((unsigned short)(v & 0xFFFF)))
                 + __half2float(__ushort_as_half((unsigned short)(v >> 16)));
        s = fmaf(pv, W[k * 16 + n], s);
    }
    frac[t] = __fdividef(1.f, 1.f + __expf(-s));
}

// ---------------- Sinkhorn: register-resident, 2 threads/sample --------------
__global__ void __launch_bounds__(256) sinkhorn_reg(
    const float* __restrict__ mat, const float* __restrict__ bids,
    const float* __restrict__ frac, float* __restrict__ outA,
    float* __restrict__ outP)
{
    const int tid = threadIdx.x;
    const int p   = tid & 1;
    const int s   = blockIdx.x * 128 + (tid >> 1);
    const float* mrow = mat + (size_t)s * 256 + p * 8;

    float K[16][8];
#pragma unroll
    for (int i = 0; i < 16; i++) {
        float4 x0 = *(const float4*)(mrow + i * 16);
        float4 x1 = *(const float4*)(mrow + i * 16 + 4);
        K[i][0] = __expf(x0.x * 10.f); K[i][1] = __expf(x0.y * 10.f);
        K[i][2] = __expf(x0.z * 10.f); K[i][3] = __expf(x0.w * 10.f);
        K[i][4] = __expf(x1.x * 10.f); K[i][5] = __expf(x1.y * 10.f);
        K[i][6] = __expf(x1.z * 10.f); K[i][7] = __expf(x1.w * 10.f);
    }

    float v[8], v16 = 1.f;
#pragma unroll
    for (int j = 0; j < 8; j++) v[j] = 1.f;
    float u[16], u16;

#pragma unroll 1
    for (int rnd = 0; rnd < 40; rnd++) {
        float r[17];
#pragma unroll
        for (int i = 0; i < 16; i++) {
            float a = K[i][0] * v[0];
#pragma unroll
            for (int j = 1; j < 8; j++) a = fmaf(K[i][j], v[j], a);
            r[i] = a;
        }
        {
            float a = v[0];
#pragma unroll
            for (int j = 1; j < 8; j++) a += v[j];
            r[16] = a;
        }
#pragma unroll
        for (int i = 0; i < 17; i++)
            r[i] += __shfl_xor_sync(0xFFFFFFFFu, r[i], 1);
#pragma unroll
        for (int i = 0; i < 16; i++) u[i] = __fdividef(1.f, r[i] + v16);
        u16 = __fdividef(16.f, r[16] + v16);

        float usum = u[0];
#pragma unroll
        for (int i = 1; i < 16; i++) usum += u[i];
#pragma unroll
        for (int j = 0; j < 8; j++) {
            float c = u16;
#pragma unroll
            for (int i = 0; i < 16; i++) c = fmaf(K[i][j], u[i], c);
            v[j] = __fdividef(1.f, c);
        }
        v16 = __fdividef(16.f, usum + u16);
    }

    const float* brow = bids + (size_t)s * 256 + p * 8;
    float* arow = outA + (size_t)s * 256 + p * 8;
    float pp[16];
#pragma unroll
    for (int i = 0; i < 16; i++) {
        float4 b0 = *(const float4*)(brow + i * 16);
        float4 b1 = *(const float4*)(brow + i * 16 + 4);
        float ui = u[i];
        float a0 = ui * K[i][0] * v[0], a1 = ui * K[i][1] * v[1];
        float a2 = ui * K[i][2] * v[2], a3 = ui * K[i][3] * v[3];
        float a4 = ui * K[i][4] * v[4], a5 = ui * K[i][5] * v[5];
        float a6 = ui * K[i][6] * v[6], a7 = ui * K[i][7] * v[7];
        *(float4*)(arow + i * 16)     = make_float4(a0, a1, a2, a3);
        *(float4*)(arow + i * 16 + 4) = make_float4(a4, a5, a6, a7);
        pp[i] = a0 * b0.x + a1 * b0.y + a2 * b0.z + a3 * b0.w
              + a4 * b1.x + a5 * b1.y + a6 * b1.z + a7 * b1.w;
    }
#pragma unroll
    for (int i = 0; i < 16; i++)
        pp[i] += __shfl_xor_sync(0xFFFFFFFFu, pp[i], 1);

    const float* frow = frac + (size_t)s * 16 + p * 8;
    float4 f0 = *(const float4*)frow;
    float4 f1 = *(const float4*)(frow + 4);
    float pay[8];
#pragma unroll
    for (int q = 0; q < 8; q++) pay[q] = p ? pp[8 + q] : pp[q];
    pay[0] *= f0.x; pay[1] *= f0.y; pay[2] *= f0.z; pay[3] *= f0.w;
    pay[4] *= f1.x; pay[5] *= f1.y; pay[6] *= f1.z; pay[7] *= f1.w;
    float* prow = outP + (size_t)s * 16 + p * 8;
    *(float4*)prow       = make_float4(pay[0], pay[1], pay[2], pay[3]);
    *(float4*)(prow + 4) = make_float4(pay[4], pay[5], pay[6], pay[7]);
}

// ---------------- launch -----------------------------------------------------
extern "C" void kernel_launch(void* const* d_in, const int* in_sizes, int n_in,
                              void* d_out, int out_size)
{
    const float* bids = (const float*)d_in[0];
    const float* aw0 = (const float*)d_in[1];  const float* ab0 = (const float*)d_in[2];
    const float* aw1 = (const float*)d_in[3];  const float* ab1 = (const float*)d_in[4];
    const float* aw2 = (const float*)d_in[5];  const float* ab2 = (const float*)d_in[6];
    const float* aw3 = (const float*)d_in[7];  const float* ab3 = (const float*)d_in[8];
    const float* pw0 = (const float*)d_in[9];  const float* pb0 = (const float*)d_in[10];
    const float* pw1 = (const float*)d_in[11]; const float* pb1 = (const float*)d_in[12];
    const float* pw2 = (const float*)d_in[13]; const float* pb2 = (const float*)d_in[14];
    const float* pw3 = (const float*)d_in[15]; const float* pb3 = (const float*)d_in[16];

    const int M = in_sizes[0] / 256;  // 32768

    void* p;
    cudaGetSymbolAddress(&p, g_x);    uint32_t* x  = (uint32_t*)p;
    cudaGetSymbolAddress(&p, g_a0);   uint32_t* a0 = (uint32_t*)p;
    cudaGetSymbolAddress(&p, g_a1);   uint32_t* a1 = (uint32_t*)p;
    cudaGetSymbolAddress(&p, g_b0);   uint32_t* b0 = (uint32_t*)p;
    cudaGetSymbolAddress(&p, g_b1);   uint32_t* b1 = (uint32_t*)p;
    cudaGetSymbolAddress(&p, g_mat);  float* mat = (float*)p;
    cudaGetSymbolAddress(&p, g_frac); float* fr  = (float*)p;
    cudaGetSymbolAddress(&p, g_wt);   uint32_t* wt = (uint32_t*)p;

    cudaFuncSetAttribute(gemm_hmma<2, 1, 128>, cudaFuncAttributeMaxDynamicSharedMemorySize, SMEM_BYTES);
    cudaFuncSetAttribute(gemm_hmma<1, 1, 128>, cudaFuncAttributeMaxDynamicSharedMemorySize, SMEM_BYTES);
    cudaFuncSetAttribute(gemm_hmma<1, 2, 256>, cudaFuncAttributeMaxDynamicSharedMemorySize, SMEM_BYTES);

    pack_x<<<(M * 256 + 255) / 256, 256>>>(bids, x, M * 256);
    pack_w_all<<<dim3(128, 7), 256>>>(aw0, aw1, aw2, aw3, pw0, pw1, pw2, wt);

    const int G = M / 64;  // 512 m-blocks
    gemm_hmma<2, 1, 128><<<dim3(1, G, 2), 256, SMEM_BYTES>>>(
        x, x, wt + OFF_AW0, wt + OFF_PW0, ab0, pb0, a0, b0);
    gemm_hmma<1, 1, 128><<<dim3(1, G, 2), 256, SMEM_BYTES>>>(
        a0, b0, wt + OFF_AW1, wt + OFF_PW1, ab1, pb1, a1, b1);
    gemm_hmma<1, 1, 128><<<dim3(1, G, 2), 256, SMEM_BYTES>>>(
        a1, b1, wt + OFF_AW2, wt + OFF_PW2, ab2, pb2, a0, b0);
    gemm_hmma<1, 2, 256><<<dim3(2, G, 1), 256, SMEM_BYTES>>>(
        a0, a0, wt + OFF_AW3, wt + OFF_AW3, ab3, ab3, mat, mat);
    pay_head<<<(M * 16 + 255) / 256, 256>>>(b0, pw3, pb3, fr, M);

    float* out = (float*)d_out;
    sinkhorn_reg<<<M / 128, 256>>>(mat, bids, fr, out, out + (size_t)M * 256);
}

// round 10
// speedup vs baseline: 1.9673x; 1.0659x over previous
#include <cuda_runtime.h>
#include <cuda_fp16.h>
#include <cstdint>
#include <math.h>

// DoubleNet (sm_103, HMMA): fp16 2-way-split GEMMs, 64x128 CTA / 32x64 warp
// tiles (2 CTA/SM, low LDS-per-MMA), inline input split, fused payment head,
// register-resident Sinkhorn.  B = 32768, D = 256, H = 128, A = I = 16.

#define MAXB 32768

__device__ uint32_t g_a0[MAXB * 128];
__device__ uint32_t g_a1[MAXB * 128];
__device__ uint32_t g_b0[MAXB * 128];
__device__ uint32_t g_b1[MAXB * 128];
__device__ float    g_mat [MAXB * 256];
__device__ float    g_frac[MAXB * 16];
__device__ uint32_t g_wt[163840];

#define OFF_AW0 0
#define OFF_AW1 32768
#define OFF_AW2 49152
#define OFF_AW3 65536
#define OFF_PW0 98304
#define OFF_PW1 131072
#define OFF_PW2 147456

// ---------------- helpers ----------------------------------------------------
__device__ __forceinline__ uint32_t smem_u32(const void* p) {
    uint32_t a;
    asm("{ .reg .u64 t; cvta.to.shared.u64 t, %1; cvt.u32.u64 %0, t; }"
        : "=r"(a) : "l"(p));
    return a;
}
__device__ __forceinline__ uint32_t packsplit(float v) {
    __half h = __float2half_rn(v);
    float hf = __half2float(h);
    __half l = __float2half_rn(v - hf);
    return (uint32_t)__half_as_ushort(h) | ((uint32_t)__half_as_ushort(l) << 16);
}
__device__ __forceinline__ float unpacksum(uint32_t v) {
    return __half2float(__ushort_as_half((unsigned short)(v & 0xFFFF)))
         + __half2float(__ushort_as_half((unsigned short)(v >> 16)));
}
__device__ __forceinline__ void mma16816_f(float* d, const uint32_t* a, const uint32_t* b) {
    asm volatile(
        "mma.sync.aligned.m16n8k16.row.col.f32.f16.f16.f32 "
        "{%0,%1,%2,%3}, {%4,%5,%6,%7}, {%8,%9}, {%0,%1,%2,%3};"
        : "+f"(d[0]), "+f"(d[1]), "+f"(d[2]), "+f"(d[3])
        : "r"(a[0]), "r"(a[1]), "r"(a[2]), "r"(a[3]), "r"(b[0]), "r"(b[1]));
}
__device__ __forceinline__ void mma16816_h(uint32_t* d, const uint32_t* a, const uint32_t* b) {
    asm volatile(
        "mma.sync.aligned.m16n8k16.row.col.f16.f16.f16.f16 "
        "{%0,%1}, {%2,%3,%4,%5}, {%6,%7}, {%0,%1};"
        : "+r"(d[0]), "+r"(d[1])
        : "r"(a[0]), "r"(a[1]), "r"(a[2]), "r"(a[3]), "r"(b[0]), "r"(b[1]));
}
#define LDSM4(R, addr) \
    asm volatile("ldmatrix.sync.aligned.m8n8.x4.shared.b16 {%0,%1,%2,%3}, [%4];" \
                 : "=r"((R)[0]), "=r"((R)[1]), "=r"((R)[2]), "=r"((R)[3]) : "r"(addr))

// ---------------- weight packing ---------------------------------------------
__global__ void pack_w_all(const float* __restrict__ aw0, const float* __restrict__ aw1,
                           const float* __restrict__ aw2, const float* __restrict__ aw3,
                           const float* __restrict__ pw0, const float* __restrict__ pw1,
                           const float* __restrict__ pw2, uint32_t* __restrict__ wt)
{
    const float* src; int K, N, off;
    switch (blockIdx.y) {
        case 0: src = aw0; K = 256; N = 128; off = OFF_AW0; break;
        case 1: src = aw1; K = 128; N = 128; off = OFF_AW1; break;
        case 2: src = aw2; K = 128; N = 128; off = OFF_AW2; break;
        case 3: src = aw3; K = 128; N = 256; off = OFF_AW3; break;
        case 4: src = pw0; K = 256; N = 128; off = OFF_PW0; break;
        case 5: src = pw1; K = 128; N = 128; off = OFF_PW1; break;
        default: src = pw2; K = 128; N = 128; off = OFF_PW2; break;
    }
    int i = blockIdx.x * 256 + threadIdx.x;
    if (i >= K * N) return;
    int n = i / K, k = i - n * K;
    wt[off + i] = packsplit(src[k * N + n]);
}

// ---------------- SMEM layout ------------------------------------------------
// Plane row stride 272 B (17*16B: ldmatrix conflict-free).
// A: 64 rows hi/lo; B: 128 rows hi/lo.
#define ROWB   272
#define APLANE 17408
#define SM_AHI 0
#define SM_ALO 17408
#define SM_BHI 34816
#define SM_BLO 69632
#define SMEM_BYTES 104448

// ROWS*32 16B-chunks total; 128 threads. F32SRC: read f32, split inline.
template <int ROWS, bool F32SRC>
__device__ __forceinline__ void load_tile(char* hi, char* lo, const void* srcv,
                                          int stride16, int tid) {
#pragma unroll
    for (int j = 0; j < ROWS / 4; j++) {
        int lin = j * 128 + tid;
        int row = lin >> 5;
        int q8  = lin & 31;
        uint32_t h0, h1, l0, l1;
        if (F32SRC) {
            float4 v = ((const float4*)srcv)[row * stride16 + q8];
            uint32_t p0 = packsplit(v.x), p1 = packsplit(v.y);
            uint32_t p2 = packsplit(v.z), p3 = packsplit(v.w);
            h0 = __byte_perm(p0, p1, 0x5410); h1 = __byte_perm(p2, p3, 0x5410);
            l0 = __byte_perm(p0, p1, 0x7632); l1 = __byte_perm(p2, p3, 0x7632);
        } else {
            uint4 v = ((const uint4*)srcv)[row * stride16 + q8];
            h0 = __byte_perm(v.x, v.y, 0x5410); h1 = __byte_perm(v.z, v.w, 0x5410);
            l0 = __byte_perm(v.x, v.y, 0x7632); l1 = __byte_perm(v.z, v.w, 0x7632);
        }
        int off = row * ROWB + q8 * 8;
        *(uint2*)(hi + off) = make_uint2(h0, h1);
        *(uint2*)(lo + off) = make_uint2(l0, l1);
    }
}

// ---------------- HMMA GEMM --------------------------------------------------
// CTA tile 64(M) x 128(N); 4 warps (2M x 2N), warp 32x64. 2 CTAs/SM.
// hi@Whi f32 accum; (hi@Wlo + lo@Whi) f16 accum, merged at end.
// PAYFUSE: on z==1, epilogue computes frac = sigmoid(acts @ pw3 + pb3).
template <int KCHUNKS, int ACT, int OUTSTRIDE, bool F32SRC, bool PAYFUSE>
__global__ void __launch_bounds__(128, 2)
gemm_hmma(const void* __restrict__ A0, const void* __restrict__ A1,
          const uint32_t* __restrict__ W0, const uint32_t* __restrict__ W1,
          const float* __restrict__ bias0, const float* __restrict__ bias1,
          void* __restrict__ out0, void* __restrict__ out1,
          const float* __restrict__ pw3, const float* __restrict__ pb3,
          float* __restrict__ fracOut)
{
    constexpr int KTE = KCHUNKS * 128;   // K elements per A row
    extern __shared__ __align__(16) char smem[];

    const void* Aact  = blockIdx.z ? A1 : A0;
    const uint32_t* Wt = blockIdx.z ? W1 : W0;
    const float* bias  = blockIdx.z ? bias1 : bias0;
    void* outp         = blockIdx.z ? out1 : out0;

    const int tid  = threadIdx.x;
    const int lane = tid & 31;
    const int w    = tid >> 5;
    const int wm   = (w & 1) * 32;    // 2 warps along M
    const int wn   = (w >> 1) * 64;   // 2 warps along N
    const int bm   = blockIdx.y * 64;
    const int noff = blockIdx.x * 128;

    float acc[2][8][4];
    uint32_t acc16[2][8][2];
#pragma unroll
    for (int i = 0; i < 2; i++)
#pragma unroll
        for (int j = 0; j < 8; j++) {
#pragma unroll
            for (int q = 0; q < 4; q++) acc[i][j][q] = 0.f;
            acc16[i][j][0] = 0u; acc16[i][j][1] = 0u;
        }

    const uint32_t sb = smem_u32(smem);
    const int l15 = lane & 15;
    const int lhi = (lane >> 4) * 16;
    const uint32_t aBase = sb + SM_AHI + (uint32_t)(wm + l15) * ROWB + lhi;
    const uint32_t bBase = sb + SM_BHI + (uint32_t)(wn + l15) * ROWB + lhi;

    for (int c = 0; c < KCHUNKS; c++) {
        if (c) __syncthreads();
        if (F32SRC)
            load_tile<64, true>(smem + SM_AHI, smem + SM_ALO,
                (const float*)Aact + (size_t)bm * KTE + c * 128, KTE / 4, tid);
        else
            load_tile<64, false>(smem + SM_AHI, smem + SM_ALO,
                (const uint32_t*)Aact + (size_t)bm * KTE + c * 128, KTE / 4, tid);
        load_tile<128, false>(smem + SM_BHI, smem + SM_BLO,
            Wt + (size_t)noff * KTE + c * 128, KTE / 4, tid);
        __syncthreads();

#pragma unroll
        for (int kk = 0; kk < 8; kk++) {
            uint32_t ahi[2][4], alo[2][4];
#pragma unroll
            for (int i = 0; i < 2; i++) {
                LDSM4(ahi[i], aBase + i * (16 * ROWB) + kk * 32);
                LDSM4(alo[i], aBase + APLANE + i * (16 * ROWB) + kk * 32);
            }
            uint32_t bhi[8][2], blo[8][2];
#pragma unroll
            for (int jj = 0; jj < 4; jj++) {
                uint32_t r[4];
                LDSM4(r, bBase + jj * (16 * ROWB) + kk * 32);
                bhi[2 * jj][0] = r[0]; bhi[2 * jj + 1][0] = r[1];
                bhi[2 * jj][1] = r[2]; bhi[2 * jj + 1][1] = r[3];
                LDSM4(r, bBase + APLANE * 2 + jj * (16 * ROWB) + kk * 32);
                blo[2 * jj][0] = r[0]; blo[2 * jj + 1][0] = r[1];
                blo[2 * jj][1] = r[2]; blo[2 * jj + 1][1] = r[3];
            }
#pragma unroll
            for (int j = 0; j < 8; j++)
#pragma unroll
                for (int i = 0; i < 2; i++) {
                    mma16816_f(acc[i][j], ahi[i], bhi[j]);
                    mma16816_h(acc16[i][j], ahi[i], blo[j]);
                    mma16816_h(acc16[i][j], alo[i], bhi[j]);
                }
        }
    }

#pragma unroll
    for (int i = 0; i < 2; i++)
#pragma unroll
        for (int j = 0; j < 8; j++) {
            float2 f0 = __half22float2(*reinterpret_cast<__half2*>(&acc16[i][j][0]));
            float2 f1 = __half22float2(*reinterpret_cast<__half2*>(&acc16[i][j][1]));
            acc[i][j][0] += f0.x; acc[i][j][1] += f0.y;
            acc[i][j][2] += f1.x; acc[i][j][3] += f1.y;
        }

    __syncthreads();

    const int r4 = lane >> 2;
    if (ACT == 1) {
        uint32_t* stage = (uint32_t*)smem;
#pragma unroll
        for (int i = 0; i < 2; i++) {
            int r0 = wm + i * 16 + r4;
#pragma unroll
            for (int j = 0; j < 8; j++) {
                int c0 = wn + j * 8 + (lane & 3) * 2;
                float b0 = bias[c0], b1 = bias[c0 + 1];
                stage[r0 * 132 + c0]           = packsplit(tanhf(acc[i][j][0] + b0));
                stage[r0 * 132 + c0 + 1]       = packsplit(tanhf(acc[i][j][1] + b1));
                stage[(r0 + 8) * 132 + c0]     = packsplit(tanhf(acc[i][j][2] + b0));
                stage[(r0 + 8) * 132 + c0 + 1] = packsplit(tanhf(acc[i][j][3] + b1));
            }
        }
        if (PAYFUSE && blockIdx.z == 1) {
            // stage holds 64x128 tanh activations (packed); compute frac.
            float* sW = (float*)(smem + SM_BHI);      // 2048 f32 = pw3 linear copy
#pragma unroll
            for (int t = 0; t < 16; t++) sW[t * 128 + tid] = pw3[t * 128 + tid];
            __syncthreads();
            const int s = tid >> 1, half = tid & 1;
            float a8[8];
#pragma unroll
            for (int j = 0; j < 8; j++) a8[j] = pb3[half * 8 + j];
            const uint32_t* srow = (uint32_t*)smem + s * 132;
#pragma unroll 8
            for (int k = 0; k < 128; k++) {
                float av = unpacksum(srow[k]);
                const float* wrow = sW + k * 16 + half * 8;
#pragma unroll
                for (int j = 0; j < 8; j++) a8[j] = fmaf(av, wrow[j], a8[j]);
            }
            float* fo = fracOut + (size_t)(bm + s) * 16 + half * 8;
#pragma unroll
            for (int j = 0; j < 8; j++)
                fo[j] = __fdividef(1.f, 1.f + __expf(-a8[j]));
        } else {
            __syncthreads();
            uint32_t* og = (uint32_t*)outp + (size_t)bm * OUTSTRIDE;
#pragma unroll
            for (int it = 0; it < 64; it++) {
                int lin = it * 128 + tid;
                int row = lin >> 7, col = lin & 127;
                og[row * OUTSTRIDE + col] = stage[row * 132 + col];
            }
        }
    } else {
        float* stage = (float*)smem;
#pragma unroll
        for (int i = 0; i < 2; i++) {
            int r0 = wm + i * 16 + r4;
#pragma unroll
            for (int j = 0; j < 8; j++) {
                int c0 = wn + j * 8 + (lane & 3) * 2;
                float b0 = bias[noff + c0], b1 = bias[noff + c0 + 1];
                stage[r0 * 132 + c0]           = acc[i][j][0] + b0;
                stage[r0 * 132 + c0 + 1]       = acc[i][j][1] + b1;
                stage[(r0 + 8) * 132 + c0]     = acc[i][j][2] + b0;
                stage[(r0 + 8) * 132 + c0 + 1] = acc[i][j][3] + b1;
            }
        }
        __syncthreads();
        float* og = (float*)outp + (size_t)bm * OUTSTRIDE + noff;
#pragma unroll
        for (int it = 0; it < 64; it++) {
            int lin = it * 128 + tid;
            int row = lin >> 7, col = lin & 127;
            og[row * OUTSTRIDE + col] = stage[row * 132 + col];
        }
    }
}

// ---------------- Sinkhorn: register-resident, 2 threads/sample --------------
__global__ void __launch_bounds__(256) sinkhorn_reg(
    const float* __restrict__ mat, const float* __restrict__ bids,
    const float* __restrict__ frac, float* __restrict__ outA,
    float* __restrict__ outP)
{
    const int tid = threadIdx.x;
    const int p   = tid & 1;
    const int s   = blockIdx.x * 128 + (tid >> 1);
    const float* mrow = mat + (size_t)s * 256 + p * 8;

    float K[16][8];
#pragma unroll
    for (int i = 0; i < 16; i++) {
        float4 x0 = *(const float4*)(mrow + i * 16);
        float4 x1 = *(const float4*)(mrow + i * 16 + 4);
        K[i][0] = __expf(x0.x * 10.f); K[i][1] = __expf(x0.y * 10.f);
        K[i][2] = __expf(x0.z * 10.f); K[i][3] = __expf(x0.w * 10.f);
        K[i][4] = __expf(x1.x * 10.f); K[i][5] = __expf(x1.y * 10.f);
        K[i][6] = __expf(x1.z * 10.f); K[i][7] = __expf(x1.w * 10.f);
    }

    float v[8], v16 = 1.f;
#pragma unroll
    for (int j = 0; j < 8; j++) v[j] = 1.f;
    float u[16], u16;

#pragma unroll 1
    for (int rnd = 0; rnd < 40; rnd++) {
        float r[17];
#pragma unroll
        for (int i = 0; i < 16; i++) {
            float a = K[i][0] * v[0];
#pragma unroll
            for (int j = 1; j < 8; j++) a = fmaf(K[i][j], v[j], a);
            r[i] = a;
        }
        {
            float a = v[0];
#pragma unroll
            for (int j = 1; j < 8; j++) a += v[j];
            r[16] = a;
        }
#pragma unroll
        for (int i = 0; i < 17; i++)
            r[i] += __shfl_xor_sync(0xFFFFFFFFu, r[i], 1);
#pragma unroll
        for (int i = 0; i < 16; i++) u[i] = __fdividef(1.f, r[i] + v16);
        u16 = __fdividef(16.f, r[16] + v16);

        float usum = u[0];
#pragma unroll
        for (int i = 1; i < 16; i++) usum += u[i];
#pragma unroll
        for (int j = 0; j < 8; j++) {
            float c = u16;
#pragma unroll
            for (int i = 0; i < 16; i++) c = fmaf(K[i][j], u[i], c);
            v[j] = __fdividef(1.f, c);
        }
        v16 = __fdividef(16.f, usum + u16);
    }

    const float* brow = bids + (size_t)s * 256 + p * 8;
    float* arow = outA + (size_t)s * 256 + p * 8;
    float pp[16];
#pragma unroll
    for (int i = 0; i < 16; i++) {
        float4 b0 = *(const float4*)(brow + i * 16);
        float4 b1 = *(const float4*)(brow + i * 16 + 4);
        float ui = u[i];
        float a0 = ui * K[i][0] * v[0], a1 = ui * K[i][1] * v[1];
        float a2 = ui * K[i][2] * v[2], a3 = ui * K[i][3] * v[3];
        float a4 = ui * K[i][4] * v[4], a5 = ui * K[i][5] * v[5];
        float a6 = ui * K[i][6] * v[6], a7 = ui * K[i][7] * v[7];
        *(float4*)(arow + i * 16)     = make_float4(a0, a1, a2, a3);
        *(float4*)(arow + i * 16 + 4) = make_float4(a4, a5, a6, a7);
        pp[i] = a0 * b0.x + a1 * b0.y + a2 * b0.z + a3 * b0.w
              + a4 * b1.x + a5 * b1.y + a6 * b1.z + a7 * b1.w;
    }
#pragma unroll
    for (int i = 0; i < 16; i++)
        pp[i] += __shfl_xor_sync(0xFFFFFFFFu, pp[i], 1);

    const float* frow = frac + (size_t)s * 16 + p * 8;
    float4 f0 = *(const float4*)frow;
    float4 f1 = *(const float4*)(frow + 4);
    float pay[8];
#pragma unroll
    for (int q = 0; q < 8; q++) pay[q] = p ? pp[8 + q] : pp[q];
    pay[0] *= f0.x; pay[1] *= f0.y; pay[2] *= f0.z; pay[3] *= f0.w;
    pay[4] *= f1.x; pay[5] *= f1.y; pay[6] *= f1.z; pay[7] *= f1.w;
    float* prow = outP + (size_t)s * 16 + p * 8;
    *(float4*)prow       = make_float4(pay[0], pay[1], pay[2], pay[3]);
    *(float4*)(prow + 4) = make_float4(pay[4], pay[5], pay[6], pay[7]);
}

// ---------------- launch -----------------------------------------------------
extern "C" void kernel_launch(void* const* d_in, const int* in_sizes, int n_in,
                              void* d_out, int out_size)
{
    const float* bids = (const float*)d_in[0];
    const float* aw0 = (const float*)d_in[1];  const float* ab0 = (const float*)d_in[2];
    const float* aw1 = (const float*)d_in[3];  const float* ab1 = (const float*)d_in[4];
    const float* aw2 = (const float*)d_in[5];  const float* ab2 = (const float*)d_in[6];
    const float* aw3 = (const float*)d_in[7];  const float* ab3 = (const float*)d_in[8];
    const float* pw0 = (const float*)d_in[9];  const float* pb0 = (const float*)d_in[10];
    const float* pw1 = (const float*)d_in[11]; const float* pb1 = (const float*)d_in[12];
    const float* pw2 = (const float*)d_in[13]; const float* pb2 = (const float*)d_in[14];
    const float* pw3 = (const float*)d_in[15]; const float* pb3 = (const float*)d_in[16];

    const int M = in_sizes[0] / 256;  // 32768

    void* p;
    cudaGetSymbolAddress(&p, g_a0);   uint32_t* a0 = (uint32_t*)p;
    cudaGetSymbolAddress(&p, g_a1);   uint32_t* a1 = (uint32_t*)p;
    cudaGetSymbolAddress(&p, g_b0);   uint32_t* b0 = (uint32_t*)p;
    cudaGetSymbolAddress(&p, g_b1);   uint32_t* b1 = (uint32_t*)p;
    cudaGetSymbolAddress(&p, g_mat);  float* mat = (float*)p;
    cudaGetSymbolAddress(&p, g_frac); float* fr  = (float*)p;
    cudaGetSymbolAddress(&p, g_wt);   uint32_t* wt = (uint32_t*)p;

    cudaFuncSetAttribute(gemm_hmma<2, 1, 128, true,  false>,
                         cudaFuncAttributeMaxDynamicSharedMemorySize, SMEM_BYTES);
    cudaFuncSetAttribute(gemm_hmma<1, 1, 128, false, false>,
                         cudaFuncAttributeMaxDynamicSharedMemorySize, SMEM_BYTES);
    cudaFuncSetAttribute(gemm_hmma<1, 1, 128, false, true>,
                         cudaFuncAttributeMaxDynamicSharedMemorySize, SMEM_BYTES);
    cudaFuncSetAttribute(gemm_hmma<1, 2, 256, false, false>,
                         cudaFuncAttributeMaxDynamicSharedMemorySize, SMEM_BYTES);

    pack_w_all<<<dim3(128, 7), 256>>>(aw0, aw1, aw2, aw3, pw0, pw1, pw2, wt);

    const int G = M / 64;  // 512 m-blocks
    // G0: bids(f32) -> a0 (alloc) / b0 (pay), K=256
    gemm_hmma<2, 1, 128, true, false><<<dim3(1, G, 2), 128, SMEM_BYTES>>>(
        bids, bids, wt + OFF_AW0, wt + OFF_PW0, ab0, pb0, a0, b0,
        nullptr, nullptr, nullptr);
    // G1
    gemm_hmma<1, 1, 128, false, false><<<dim3(1, G, 2), 128, SMEM_BYTES>>>(
        a0, b0, wt + OFF_AW1, wt + OFF_PW1, ab1, pb1, a1, b1,
        nullptr, nullptr, nullptr);
    // G2: alloc out -> a0; pay branch computes frac inline
    gemm_hmma<1, 1, 128, false, true><<<dim3(1, G, 2), 128, SMEM_BYTES>>>(
        a1, b1, wt + OFF_AW2, wt + OFF_PW2, ab2, pb2, a0, b0,
        pw3, pb3, fr);
    // G3: mat = a0 @ aw3 + ab3 (N=256, f32 out)
    gemm_hmma<1, 2, 256, false, false><<<dim3(2, G, 1), 128, SMEM_BYTES>>>(
        a0, a0, wt + OFF_AW3, wt + OFF_AW3, ab3, ab3, mat, mat,
        nullptr, nullptr, nullptr);

    float* out = (float*)d_out;
    sinkhorn_reg<<<M / 128, 256>>>(mat, bids, fr, out, out + (size_t)M * 256);
}

// round 11
// speedup vs baseline: 2.1364x; 1.0859x over previous
#include <cuda_runtime.h>
#include <cuda_fp16.h>
#include <cstdint>
#include <math.h>

// DoubleNet (sm_103, HMMA): fp16 2-way-split GEMMs, planar hi/lo storage with
// cp.async tile loads, 64x128 CTA / 32x32 warp tiles (16 warps/SM), fused
// payment head, register-resident Sinkhorn.
// B = 32768, D = 256, H = 128, A = I = 16, EPS = 0.1

#define MAXB 32768

// activations: hi plane [M*128] then lo plane [M*128]
__device__ __half g_a0[MAXB * 256];
__device__ __half g_a1[MAXB * 256];
__device__ __half g_b0[MAXB * 256];
__device__ __half g_b1[MAXB * 256];
__device__ float  g_mat [MAXB * 256];
__device__ float  g_frac[MAXB * 16];
__device__ __half g_wt[327680];   // per-weight: hi plane [N*K], lo plane [N*K]

// offsets in halves
#define OFF_AW0 0
#define OFF_AW1 65536
#define OFF_AW2 98304
#define OFF_AW3 131072
#define OFF_PW0 196608
#define OFF_PW1 262144
#define OFF_PW2 294912

// ---------------- helpers ----------------------------------------------------
__device__ __forceinline__ uint32_t smem_u32(const void* p) {
    uint32_t a;
    asm("{ .reg .u64 t; cvta.to.shared.u64 t, %1; cvt.u32.u64 %0, t; }"
        : "=r"(a) : "l"(p));
    return a;
}
// split two f32 into (hi-pair, lo-pair) packed u32s
__device__ __forceinline__ void split2(float x0, float x1, uint32_t& hw, uint32_t& lw) {
    __half h0 = __float2half_rn(x0), h1 = __float2half_rn(x1);
    __half l0 = __float2half_rn(x0 - __half2float(h0));
    __half l1 = __float2half_rn(x1 - __half2float(h1));
    hw = (uint32_t)__half_as_ushort(h0) | ((uint32_t)__half_as_ushort(h1) << 16);
    lw = (uint32_t)__half_as_ushort(l0) | ((uint32_t)__half_as_ushort(l1) << 16);
}
__device__ __forceinline__ void mma16816_f(float* d, const uint32_t* a, const uint32_t* b) {
    asm volatile(
        "mma.sync.aligned.m16n8k16.row.col.f32.f16.f16.f32 "
        "{%0,%1,%2,%3}, {%4,%5,%6,%7}, {%8,%9}, {%0,%1,%2,%3};"
        : "+f"(d[0]), "+f"(d[1]), "+f"(d[2]), "+f"(d[3])
        : "r"(a[0]), "r"(a[1]), "r"(a[2]), "r"(a[3]), "r"(b[0]), "r"(b[1]));
}
__device__ __forceinline__ void mma16816_h(uint32_t* d, const uint32_t* a, const uint32_t* b) {
    asm volatile(
        "mma.sync.aligned.m16n8k16.row.col.f16.f16.f16.f16 "
        "{%0,%1}, {%2,%3,%4,%5}, {%6,%7}, {%0,%1};"
        : "+r"(d[0]), "+r"(d[1])
        : "r"(a[0]), "r"(a[1]), "r"(a[2]), "r"(a[3]), "r"(b[0]), "r"(b[1]));
}
#define LDSM4(R, addr) \
    asm volatile("ldmatrix.sync.aligned.m8n8.x4.shared.b16 {%0,%1,%2,%3}, [%4];" \
                 : "=r"((R)[0]), "=r"((R)[1]), "=r"((R)[2]), "=r"((R)[3]) : "r"(addr))
#define CP_ASYNC16(dst, src) \
    asm volatile("cp.async.cg.shared.global [%0], [%1], 16;" :: "r"(dst), "l"(src))
#define CP_COMMIT() asm volatile("cp.async.commit_group;")
#define CP_WAIT0()  asm volatile("cp.async.wait_group 0;")

// ---------------- weight packing (planar) ------------------------------------
__global__ void pack_w_all(const float* __restrict__ aw0, const float* __restrict__ aw1,
                           const float* __restrict__ aw2, const float* __restrict__ aw3,
                           const float* __restrict__ pw0, const float* __restrict__ pw1,
                           const float* __restrict__ pw2, __half* __restrict__ wt)
{
    const float* src; int K, N, off;
    switch (blockIdx.y) {
        case 0: src = aw0; K = 256; N = 128; off = OFF_AW0; break;
        case 1: src = aw1; K = 128; N = 128; off = OFF_AW1; break;
        case 2: src = aw2; K = 128; N = 128; off = OFF_AW2; break;
        case 3: src = aw3; K = 128; N = 256; off = OFF_AW3; break;
        case 4: src = pw0; K = 256; N = 128; off = OFF_PW0; break;
        case 5: src = pw1; K = 128; N = 128; off = OFF_PW1; break;
        default: src = pw2; K = 128; N = 128; off = OFF_PW2; break;
    }
    int i = blockIdx.x * 256 + threadIdx.x;
    if (i >= K * N) return;
    int n = i / K, k = i - n * K;
    float v = src[k * N + n];
    __half h = __float2half_rn(v);
    wt[off + i]         = h;
    wt[off + N * K + i] = __float2half_rn(v - __half2float(h));
}

// ---------------- SMEM layout ------------------------------------------------
// Plane row stride 272 B (17*16B: ldmatrix conflict-free).
#define ROWB   272
#define APLANE 17408
#define SM_AHI 0
#define SM_ALO 17408
#define SM_BHI 34816
#define SM_BLO 69632
#define SMEM_BYTES 104448

// cp.async loader: ROWS rows x 128 halves -> padded SMEM plane. 256 threads.
template <int ROWS>
__device__ __forceinline__ void cpa_plane(uint32_t dst, const __half* __restrict__ src,
                                          int stride_h, int tid) {
#pragma unroll
    for (int j = 0; j < ROWS / 16; j++) {
        int lin = j * 256 + tid;
        int row = lin >> 4;
        int q   = lin & 15;
        CP_ASYNC16(dst + row * ROWB + q * 16, src + row * stride_h + q * 8);
    }
}

// manual f32 loader (G0 A-tile): 64 rows x KTE f32, split inline to hi/lo planes
__device__ __forceinline__ void load_f32_pair(char* hi, char* lo,
                                              const float4* __restrict__ src,
                                              int stride16, int tid) {
#pragma unroll
    for (int j = 0; j < 8; j++) {
        int lin = j * 256 + tid;
        int row = lin >> 5;
        int g   = lin & 31;
        float4 v = src[row * stride16 + g];
        uint32_t h0, l0, h1, l1;
        split2(v.x, v.y, h0, l0);
        split2(v.z, v.w, h1, l1);
        int off = row * ROWB + g * 8;
        *(uint2*)(hi + off) = make_uint2(h0, h1);
        *(uint2*)(lo + off) = make_uint2(l0, l1);
    }
}

// ---------------- HMMA GEMM --------------------------------------------------
// CTA 64(M) x 128(N); 256 threads, 8 warps (2M x 4N), warp 32x32; 2 CTA/SM.
// hi@Whi f32 accum; (hi@Wlo + lo@Whi) f16 accum, merged at end.
template <int KCHUNKS, int ACT, int OUTSTRIDE, bool F32SRC, bool PAYFUSE>
__global__ void __launch_bounds__(256, 2)
gemm_hmma(const void* __restrict__ Ahi0, const void* __restrict__ Alo0,
          const void* __restrict__ Ahi1, const void* __restrict__ Alo1,
          const __half* __restrict__ Whi0, const __half* __restrict__ Wlo0,
          const __half* __restrict__ Whi1, const __half* __restrict__ Wlo1,
          const float* __restrict__ bias0, const float* __restrict__ bias1,
          void* __restrict__ outH0, void* __restrict__ outL0,
          void* __restrict__ outH1, void* __restrict__ outL1,
          const float* __restrict__ pw3, const float* __restrict__ pb3,
          float* __restrict__ fracOut)
{
    constexpr int KTE = KCHUNKS * 128;
    extern __shared__ __align__(16) char smem[];

    const void* Ahi = blockIdx.z ? Ahi1 : Ahi0;
    const void* Alo = blockIdx.z ? Alo1 : Alo0;
    const __half* Whi = blockIdx.z ? Whi1 : Whi0;
    const __half* Wlo = blockIdx.z ? Wlo1 : Wlo0;
    const float* bias = blockIdx.z ? bias1 : bias0;
    void* outH        = blockIdx.z ? outH1 : outH0;
    void* outL        = blockIdx.z ? outL1 : outL0;

    const int tid  = threadIdx.x;
    const int lane = tid & 31;
    const int w    = tid >> 5;
    const int wm   = (w & 1) * 32;    // 2 warps along M
    const int wn   = (w >> 1) * 32;   // 4 warps along N
    const int bm   = blockIdx.y * 64;
    const int noff = blockIdx.x * 128;

    float acc[2][4][4];
    uint32_t acc16[2][4][2];
#pragma unroll
    for (int i = 0; i < 2; i++)
#pragma unroll
        for (int j = 0; j < 4; j++) {
#pragma unroll
            for (int q = 0; q < 4; q++) acc[i][j][q] = 0.f;
            acc16[i][j][0] = 0u; acc16[i][j][1] = 0u;
        }

    const uint32_t sb = smem_u32(smem);
    const int l15 = lane & 15;
    const int lhi = (lane >> 4) * 16;
    const uint32_t aBase = sb + SM_AHI + (uint32_t)(wm + l15) * ROWB + lhi;
    const uint32_t bBase = sb + SM_BHI + (uint32_t)(wn + l15) * ROWB + lhi;

    for (int c = 0; c < KCHUNKS; c++) {
        if (c) __syncthreads();
        // B tiles via cp.async (planar weights)
        cpa_plane<128>(sb + SM_BHI, Whi + (size_t)noff * KTE + c * 128, KTE, tid);
        cpa_plane<128>(sb + SM_BLO, Wlo + (size_t)noff * KTE + c * 128, KTE, tid);
        // A tiles
        if (F32SRC) {
            load_f32_pair(smem + SM_AHI, smem + SM_ALO,
                (const float4*)((const float*)Ahi + (size_t)bm * KTE + c * 128),
                KTE / 4, tid);
        } else {
            cpa_plane<64>(sb + SM_AHI, (const __half*)Ahi + (size_t)bm * 128, 128, tid);
            cpa_plane<64>(sb + SM_ALO, (const __half*)Alo + (size_t)bm * 128, 128, tid);
        }
        CP_COMMIT();
        CP_WAIT0();
        __syncthreads();

#pragma unroll
        for (int kk = 0; kk < 8; kk++) {
            uint32_t ahi[2][4], alo[2][4];
#pragma unroll
            for (int i = 0; i < 2; i++) {
                LDSM4(ahi[i], aBase + i * (16 * ROWB) + kk * 32);
                LDSM4(alo[i], aBase + APLANE + i * (16 * ROWB) + kk * 32);
            }
            uint32_t bhi[4][2], blo[4][2];
#pragma unroll
            for (int jj = 0; jj < 2; jj++) {
                uint32_t r[4];
                LDSM4(r, bBase + jj * (16 * ROWB) + kk * 32);
                bhi[2 * jj][0] = r[0]; bhi[2 * jj + 1][0] = r[1];
                bhi[2 * jj][1] = r[2]; bhi[2 * jj + 1][1] = r[3];
                LDSM4(r, bBase + APLANE * 2 + jj * (16 * ROWB) + kk * 32);
                blo[2 * jj][0] = r[0]; blo[2 * jj + 1][0] = r[1];
                blo[2 * jj][1] = r[2]; blo[2 * jj + 1][1] = r[3];
            }
#pragma unroll
            for (int j = 0; j < 4; j++)
#pragma unroll
                for (int i = 0; i < 2; i++) {
                    mma16816_f(acc[i][j], ahi[i], bhi[j]);
                    mma16816_h(acc16[i][j], ahi[i], blo[j]);
                    mma16816_h(acc16[i][j], alo[i], bhi[j]);
                }
        }
    }

#pragma unroll
    for (int i = 0; i < 2; i++)
#pragma unroll
        for (int j = 0; j < 4; j++) {
            float2 f0 = __half22float2(*reinterpret_cast<__half2*>(&acc16[i][j][0]));
            float2 f1 = __half22float2(*reinterpret_cast<__half2*>(&acc16[i][j][1]));
            acc[i][j][0] += f0.x; acc[i][j][1] += f0.y;
            acc[i][j][2] += f1.x; acc[i][j][3] += f1.y;
        }

    __syncthreads();   // tiles consumed; smem reused for staging

    const int r4 = lane >> 2;
    if (ACT == 1) {
        // stage: hi plane u32[64][68] at 0, lo plane at +17408
        uint32_t* stgH = (uint32_t*)smem;
        uint32_t* stgL = (uint32_t*)(smem + APLANE);
#pragma unroll
        for (int i = 0; i < 2; i++) {
            int r0 = wm + i * 16 + r4;
#pragma unroll
            for (int j = 0; j < 4; j++) {
                int c0 = wn + j * 8 + (lane & 3) * 2;
                float b0 = bias[c0], b1 = bias[c0 + 1];
                uint32_t hw, lw;
                split2(tanhf(acc[i][j][0] + b0), tanhf(acc[i][j][1] + b1), hw, lw);
                stgH[r0 * 68 + (c0 >> 1)] = hw;
                stgL[r0 * 68 + (c0 >> 1)] = lw;
                split2(tanhf(acc[i][j][2] + b0), tanhf(acc[i][j][3] + b1), hw, lw);
                stgH[(r0 + 8) * 68 + (c0 >> 1)] = hw;
                stgL[(r0 + 8) * 68 + (c0 >> 1)] = lw;
            }
        }
        if (PAYFUSE && blockIdx.z == 1) {
            float* sW = (float*)(smem + SM_BHI);   // 2048 f32 pw3 copy
#pragma unroll
            for (int t = 0; t < 8; t++) sW[t * 256 + tid] = pw3[t * 256 + tid];
            __syncthreads();
            const int s = tid >> 2, q = tid & 3;
            const __half* hh = (const __half*)stgH + s * 136;
            const __half* ll = (const __half*)stgL + s * 136;
            float a4[4];
#pragma unroll
            for (int j = 0; j < 4; j++) a4[j] = pb3[q * 4 + j];
#pragma unroll 8
            for (int k = 0; k < 128; k++) {
                float av = __half2float(hh[k]) + __half2float(ll[k]);
                const float* wr = sW + k * 16 + q * 4;
#pragma unroll
                for (int j = 0; j < 4; j++) a4[j] = fmaf(av, wr[j], a4[j]);
            }
            float* fo = fracOut + (size_t)(bm + s) * 16 + q * 4;
#pragma unroll
            for (int j = 0; j < 4; j++)
                fo[j] = __fdividef(1.f, 1.f + __expf(-a4[j]));
        } else {
            __syncthreads();
            uint32_t* ogH = (uint32_t*)((__half*)outH + (size_t)bm * 128);
            uint32_t* ogL = (uint32_t*)((__half*)outL + (size_t)bm * 128);
#pragma unroll
            for (int it = 0; it < 16; it++) {
                int lin = it * 256 + tid;
                int row = lin >> 6, col = lin & 63;
                ogH[row * 64 + col] = stgH[row * 68 + col];
                ogL[row * 64 + col] = stgL[row * 68 + col];
            }
        }
    } else {
        float* stage = (float*)smem;   // 64 x 132
#pragma unroll
        for (int i = 0; i < 2; i++) {
            int r0 = wm + i * 16 + r4;
#pragma unroll
            for (int j = 0; j < 4; j++) {
                int c0 = wn + j * 8 + (lane & 3) * 2;
                float b0 = bias[noff + c0], b1 = bias[noff + c0 + 1];
                stage[r0 * 132 + c0]           = acc[i][j][0] + b0;
                stage[r0 * 132 + c0 + 1]       = acc[i][j][1] + b1;
                stage[(r0 + 8) * 132 + c0]     = acc[i][j][2] + b0;
                stage[(r0 + 8) * 132 + c0 + 1] = acc[i][j][3] + b1;
            }
        }
        __syncthreads();
        float* og = (float*)outH + (size_t)bm * OUTSTRIDE + noff;
#pragma unroll
        for (int it = 0; it < 32; it++) {
            int lin = it * 256 + tid;
            int row = lin >> 7, col = lin & 127;
            og[row * OUTSTRIDE + col] = stage[row * 132 + col];
        }
    }
}

// ---------------- Sinkhorn: register-resident, 2 threads/sample --------------
__global__ void __launch_bounds__(256) sinkhorn_reg(
    const float* __restrict__ mat, const float* __restrict__ bids,
    const float* __restrict__ frac, float* __restrict__ outA,
    float* __restrict__ outP)
{
    const int tid = threadIdx.x;
    const int p   = tid & 1;
    const int s   = blockIdx.x * 128 + (tid >> 1);
    const float* mrow = mat + (size_t)s * 256 + p * 8;

    float K[16][8];
#pragma unroll
    for (int i = 0; i < 16; i++) {
        float4 x0 = *(const float4*)(mrow + i * 16);
        float4 x1 = *(const float4*)(mrow + i * 16 + 4);
        K[i][0] = __expf(x0.x * 10.f); K[i][1] = __expf(x0.y * 10.f);
        K[i][2] = __expf(x0.z * 10.f); K[i][3] = __expf(x0.w * 10.f);
        K[i][4] = __expf(x1.x * 10.f); K[i][5] = __expf(x1.y * 10.f);
        K[i][6] = __expf(x1.z * 10.f); K[i][7] = __expf(x1.w * 10.f);
    }

    float v[8], v16 = 1.f;
#pragma unroll
    for (int j = 0; j < 8; j++) v[j] = 1.f;
    float u[16], u16;

#pragma unroll 1
    for (int rnd = 0; rnd < 40; rnd++) {
        float r[17];
#pragma unroll
        for (int i = 0; i < 16; i++) {
            float a = K[i][0] * v[0];
#pragma unroll
            for (int j = 1; j < 8; j++) a = fmaf(K[i][j], v[j], a);
            r[i] = a;
        }
        {
            float a = v[0];
#pragma unroll
            for (int j = 1; j < 8; j++) a += v[j];
            r[16] = a;
        }
#pragma unroll
        for (int i = 0; i < 17; i++)
            r[i] += __shfl_xor_sync(0xFFFFFFFFu, r[i], 1);
#pragma unroll
        for (int i = 0; i < 16; i++) u[i] = __fdividef(1.f, r[i] + v16);
        u16 = __fdividef(16.f, r[16] + v16);

        float usum = u[0];
#pragma unroll
        for (int i = 1; i < 16; i++) usum += u[i];
#pragma unroll
        for (int j = 0; j < 8; j++) {
            float c = u16;
#pragma unroll
            for (int i = 0; i < 16; i++) c = fmaf(K[i][j], u[i], c);
            v[j] = __fdividef(1.f, c);
        }
        v16 = __fdividef(16.f, usum + u16);
    }

    const float* brow = bids + (size_t)s * 256 + p * 8;
    float* arow = outA + (size_t)s * 256 + p * 8;
    float pp[16];
#pragma unroll
    for (int i = 0; i < 16; i++) {
        float4 b0 = *(const float4*)(brow + i * 16);
        float4 b1 = *(const float4*)(brow + i * 16 + 4);
        float ui = u[i];
        float a0 = ui * K[i][0] * v[0], a1 = ui * K[i][1] * v[1];
        float a2 = ui * K[i][2] * v[2], a3 = ui * K[i][3] * v[3];
        float a4 = ui * K[i][4] * v[4], a5 = ui * K[i][5] * v[5];
        float a6 = ui * K[i][6] * v[6], a7 = ui * K[i][7] * v[7];
        *(float4*)(arow + i * 16)     = make_float4(a0, a1, a2, a3);
        *(float4*)(arow + i * 16 + 4) = make_float4(a4, a5, a6, a7);
        pp[i] = a0 * b0.x + a1 * b0.y + a2 * b0.z + a3 * b0.w
              + a4 * b1.x + a5 * b1.y + a6 * b1.z + a7 * b1.w;
    }
#pragma unroll
    for (int i = 0; i < 16; i++)
        pp[i] += __shfl_xor_sync(0xFFFFFFFFu, pp[i], 1);

    const float* frow = frac + (size_t)s * 16 + p * 8;
    float4 f0 = *(const float4*)frow;
    float4 f1 = *(const float4*)(frow + 4);
    float pay[8];
#pragma unroll
    for (int q = 0; q < 8; q++) pay[q] = p ? pp[8 + q] : pp[q];
    pay[0] *= f0.x; pay[1] *= f0.y; pay[2] *= f0.z; pay[3] *= f0.w;
    pay[4] *= f1.x; pay[5] *= f1.y; pay[6] *= f1.z; pay[7] *= f1.w;
    float* prow = outP + (size_t)s * 16 + p * 8;
    *(float4*)prow       = make_float4(pay[0], pay[1], pay[2], pay[3]);
    *(float4*)(prow + 4) = make_float4(pay[4], pay[5], pay[6], pay[7]);
}

// ---------------- launch -----------------------------------------------------
extern "C" void kernel_launch(void* const* d_in, const int* in_sizes, int n_in,
                              void* d_out, int out_size)
{
    const float* bids = (const float*)d_in[0];
    const float* aw0 = (const float*)d_in[1];  const float* ab0 = (const float*)d_in[2];
    const float* aw1 = (const float*)d_in[3];  const float* ab1 = (const float*)d_in[4];
    const float* aw2 = (const float*)d_in[5];  const float* ab2 = (const float*)d_in[6];
    const float* aw3 = (const float*)d_in[7];  const float* ab3 = (const float*)d_in[8];
    const float* pw0 = (const float*)d_in[9];  const float* pb0 = (const float*)d_in[10];
    const float* pw1 = (const float*)d_in[11]; const float* pb1 = (const float*)d_in[12];
    const float* pw2 = (const float*)d_in[13]; const float* pb2 = (const float*)d_in[14];
    const float* pw3 = (const float*)d_in[15]; const float* pb3 = (const float*)d_in[16];

    const int M = in_sizes[0] / 256;  // 32768

    void* p;
    cudaGetSymbolAddress(&p, g_a0);   __half* a0 = (__half*)p;
    cudaGetSymbolAddress(&p, g_a1);   __half* a1 = (__half*)p;
    cudaGetSymbolAddress(&p, g_b0);   __half* b0 = (__half*)p;
    cudaGetSymbolAddress(&p, g_b1);   __half* b1 = (__half*)p;
    cudaGetSymbolAddress(&p, g_mat);  float* mat = (float*)p;
    cudaGetSymbolAddress(&p, g_frac); float* fr  = (float*)p;
    cudaGetSymbolAddress(&p, g_wt);   __half* wt = (__half*)p;

    __half* a0lo = a0 + (size_t)M * 128;
    __half* a1lo = a1 + (size_t)M * 128;
    __half* b0lo = b0 + (size_t)M * 128;
    __half* b1lo = b1 + (size_t)M * 128;

    cudaFuncSetAttribute(gemm_hmma<2, 1, 128, true,  false>,
                         cudaFuncAttributeMaxDynamicSharedMemorySize, SMEM_BYTES);
    cudaFuncSetAttribute(gemm_hmma<1, 1, 128, false, false>,
                         cudaFuncAttributeMaxDynamicSharedMemorySize, SMEM_BYTES);
    cudaFuncSetAttribute(gemm_hmma<1, 1, 128, false, true>,
                         cudaFuncAttributeMaxDynamicSharedMemorySize, SMEM_BYTES);
    cudaFuncSetAttribute(gemm_hmma<1, 2, 256, false, false>,
                         cudaFuncAttributeMaxDynamicSharedMemorySize, SMEM_BYTES);

    pack_w_all<<<dim3(128, 7), 256>>>(aw0, aw1, aw2, aw3, pw0, pw1, pw2, wt);

    const int G = M / 64;  // 512 m-blocks
    // G0: bids (f32) -> a0/b0 planes. Whi/Wlo planes per net.
    gemm_hmma<2, 1, 128, true, false><<<dim3(1, G, 2), 256, SMEM_BYTES>>>(
        bids, nullptr, bids, nullptr,
        wt + OFF_AW0, wt + OFF_AW0 + 32768, wt + OFF_PW0, wt + OFF_PW0 + 32768,
        ab0, pb0, a0, a0lo, b0, b0lo, nullptr, nullptr, nullptr);
    // G1
    gemm_hmma<1, 1, 128, false, false><<<dim3(1, G, 2), 256, SMEM_BYTES>>>(
        a0, a0lo, b0, b0lo,
        wt + OFF_AW1, wt + OFF_AW1 + 16384, wt + OFF_PW1, wt + OFF_PW1 + 16384,
        ab1, pb1, a1, a1lo, b1, b1lo, nullptr, nullptr, nullptr);
    // G2: alloc out -> a0 planes; pay branch computes frac inline
    gemm_hmma<1, 1, 128, false, true><<<dim3(1, G, 2), 256, SMEM_BYTES>>>(
        a1, a1lo, b1, b1lo,
        wt + OFF_AW2, wt + OFF_AW2 + 16384, wt + OFF_PW2, wt + OFF_PW2 + 16384,
        ab2, pb2, a0, a0lo, b0, b0lo, pw3, pb3, fr);
    // G3: mat = a0 @ aw3 + ab3 (N=256 split over blockIdx.x, f32 out)
    gemm_hmma<1, 2, 256, false, false><<<dim3(2, G, 1), 256, SMEM_BYTES>>>(
        a0, a0lo, a0, a0lo,
        wt + OFF_AW3, wt + OFF_AW3 + 32768, wt + OFF_AW3, wt + OFF_AW3 + 32768,
        ab3, ab3, mat, nullptr, mat, nullptr, nullptr, nullptr, nullptr);

    float* out = (float*)d_out;
    sinkhorn_reg<<<M / 128, 256>>>(mat, bids, fr, out, out + (size_t)M * 256);
}

// round 12
// speedup vs baseline: 2.4408x; 1.1425x over previous
#include <cuda_runtime.h>
#include <cuda_fp16.h>
#include <cstdint>
#include <math.h>

// DoubleNet (sm_103, HMMA): fully layer-fused MLP kernel. One CTA carries a
// 64-sample m-block through all 4 layers of its net; activations live in SMEM
// (planar hi/lo, ldmatrix-ready); next-layer weights cp.async-prefetched during
// the epilogue. fp16 2-way-split products (hi@Whi f32-accum + corrections
// f16-accum). Register-resident Sinkhorn. B=32768, D=256, H=128, A=I=16.

#define MAXB 32768

__device__ float  g_mat [MAXB * 256];
__device__ float  g_frac[MAXB * 16];
__device__ __half g_wt[327680];   // per-weight: hi plane [N*K], lo plane [N*K]

// offsets in halves
#define OFF_AW0 0
#define OFF_AW1 65536
#define OFF_AW2 98304
#define OFF_AW3 131072
#define OFF_PW0 196608
#define OFF_PW1 262144
#define OFF_PW2 294912

// ---------------- helpers ----------------------------------------------------
__device__ __forceinline__ uint32_t smem_u32(const void* p) {
    uint32_t a;
    asm("{ .reg .u64 t; cvta.to.shared.u64 t, %1; cvt.u32.u64 %0, t; }"
        : "=r"(a) : "l"(p));
    return a;
}
__device__ __forceinline__ void split2(float x0, float x1, uint32_t& hw, uint32_t& lw) {
    __half h0 = __float2half_rn(x0), h1 = __float2half_rn(x1);
    __half l0 = __float2half_rn(x0 - __half2float(h0));
    __half l1 = __float2half_rn(x1 - __half2float(h1));
    hw = (uint32_t)__half_as_ushort(h0) | ((uint32_t)__half_as_ushort(h1) << 16);
    lw = (uint32_t)__half_as_ushort(l0) | ((uint32_t)__half_as_ushort(l1) << 16);
}
__device__ __forceinline__ void mma16816_f(float* d, const uint32_t* a, const uint32_t* b) {
    asm volatile(
        "mma.sync.aligned.m16n8k16.row.col.f32.f16.f16.f32 "
        "{%0,%1,%2,%3}, {%4,%5,%6,%7}, {%8,%9}, {%0,%1,%2,%3};"
        : "+f"(d[0]), "+f"(d[1]), "+f"(d[2]), "+f"(d[3])
        : "r"(a[0]), "r"(a[1]), "r"(a[2]), "r"(a[3]), "r"(b[0]), "r"(b[1]));
}
__device__ __forceinline__ void mma16816_h(uint32_t* d, const uint32_t* a, const uint32_t* b) {
    asm volatile(
        "mma.sync.aligned.m16n8k16.row.col.f16.f16.f16.f16 "
        "{%0,%1}, {%2,%3,%4,%5}, {%6,%7}, {%0,%1};"
        : "+r"(d[0]), "+r"(d[1])
        : "r"(a[0]), "r"(a[1]), "r"(a[2]), "r"(a[3]), "r"(b[0]), "r"(b[1]));
}
#define LDSM4(R, addr) \
    asm volatile("ldmatrix.sync.aligned.m8n8.x4.shared.b16 {%0,%1,%2,%3}, [%4];" \
                 : "=r"((R)[0]), "=r"((R)[1]), "=r"((R)[2]), "=r"((R)[3]) : "r"(addr))
#define CP_ASYNC16(dst, src) \
    asm volatile("cp.async.cg.shared.global [%0], [%1], 16;" :: "r"(dst), "l"(src))
#define CP_COMMIT() asm volatile("cp.async.commit_group;")
#define CP_WAIT0()  asm volatile("cp.async.wait_group 0;")

// ---------------- weight packing (planar) ------------------------------------
__global__ void pack_w_all(const float* __restrict__ aw0, const float* __restrict__ aw1,
                           const float* __restrict__ aw2, const float* __restrict__ aw3,
                           const float* __restrict__ pw0, const float* __restrict__ pw1,
                           const float* __restrict__ pw2, __half* __restrict__ wt)
{
    const float* src; int K, N, off;
    switch (blockIdx.y) {
        case 0: src = aw0; K = 256; N = 128; off = OFF_AW0; break;
        case 1: src = aw1; K = 128; N = 128; off = OFF_AW1; break;
        case 2: src = aw2; K = 128; N = 128; off = OFF_AW2; break;
        case 3: src = aw3; K = 128; N = 256; off = OFF_AW3; break;
        case 4: src = pw0; K = 256; N = 128; off = OFF_PW0; break;
        case 5: src = pw1; K = 128; N = 128; off = OFF_PW1; break;
        default: src = pw2; K = 128; N = 128; off = OFF_PW2; break;
    }
    int i = blockIdx.x * 256 + threadIdx.x;
    if (i >= K * N) return;
    int n = i / K, k = i - n * K;
    float v = src[k * N + n];
    __half h = __float2half_rn(v);
    wt[off + i]         = h;
    wt[off + N * K + i] = __float2half_rn(v - __half2float(h));
}

// ---------------- SMEM layout ------------------------------------------------
#define ROWB   272
#define APLANE 17408
#define SM_AHI 0
#define SM_ALO 17408
#define SM_BHI 34816
#define SM_BLO 69632
#define SMEM_BYTES 104448

// 128 rows x 128 halves -> padded plane via cp.async. 256 threads.
__device__ __forceinline__ void cpa128(uint32_t dst, const __half* __restrict__ src,
                                       int stride_h, int tid) {
#pragma unroll
    for (int j = 0; j < 8; j++) {
        int lin = j * 256 + tid;
        int row = lin >> 4;
        int q   = lin & 15;
        CP_ASYNC16(dst + row * ROWB + q * 16, src + row * stride_h + q * 8);
    }
}
// both W planes + commit
__device__ __forceinline__ void load_w(uint32_t sb, const __half* __restrict__ whi,
                                       const __half* __restrict__ wlo,
                                       int noff, int koff, int K, int tid) {
    cpa128(sb + SM_BHI, whi + (size_t)noff * K + koff, K, tid);
    cpa128(sb + SM_BLO, wlo + (size_t)noff * K + koff, K, tid);
    CP_COMMIT();
}
// 64 rows of f32 (chunk of 128 cols), split inline to hi/lo planes
__device__ __forceinline__ void load_f32_pair(char* hi, char* lo,
                                              const float4* __restrict__ src,
                                              int stride16, int tid) {
#pragma unroll
    for (int j = 0; j < 8; j++) {
        int lin = j * 256 + tid;
        int row = lin >> 5;
        int g   = lin & 31;
        float4 v = src[row * stride16 + g];
        uint32_t h0, l0, h1, l1;
        split2(v.x, v.y, h0, l0);
        split2(v.z, v.w, h1, l1);
        int off = row * ROWB + g * 8;
        *(uint2*)(hi + off) = make_uint2(h0, h1);
        *(uint2*)(lo + off) = make_uint2(l0, l1);
    }
}

// ---------------- MMA tile ----------------------------------------------------
struct Acc {
    float    f[2][4][4];
    uint32_t h[2][4][2];
    __device__ __forceinline__ void zero() {
#pragma unroll
        for (int i = 0; i < 2; i++)
#pragma unroll
            for (int j = 0; j < 4; j++) {
#pragma unroll
                for (int q = 0; q < 4; q++) f[i][j][q] = 0.f;
                h[i][j][0] = 0u; h[i][j][1] = 0u;
            }
    }
    __device__ __forceinline__ void merge() {
#pragma unroll
        for (int i = 0; i < 2; i++)
#pragma unroll
            for (int j = 0; j < 4; j++) {
                float2 f0 = __half22float2(*reinterpret_cast<__half2*>(&h[i][j][0]));
                float2 f1 = __half22float2(*reinterpret_cast<__half2*>(&h[i][j][1]));
                f[i][j][0] += f0.x; f[i][j][1] += f0.y;
                f[i][j][2] += f1.x; f[i][j][3] += f1.y;
            }
    }
};

__device__ __forceinline__ void mma_phase(Acc& A, uint32_t aBase, uint32_t bBase) {
#pragma unroll
    for (int kk = 0; kk < 8; kk++) {
        uint32_t ahi[2][4], alo[2][4];
#pragma unroll
        for (int i = 0; i < 2; i++) {
            LDSM4(ahi[i], aBase + i * (16 * ROWB) + kk * 32);
            LDSM4(alo[i], aBase + APLANE + i * (16 * ROWB) + kk * 32);
        }
        uint32_t bhi[4][2], blo[4][2];
#pragma unroll
        for (int jj = 0; jj < 2; jj++) {
            uint32_t r[4];
            LDSM4(r, bBase + jj * (16 * ROWB) + kk * 32);
            bhi[2 * jj][0] = r[0]; bhi[2 * jj + 1][0] = r[1];
            bhi[2 * jj][1] = r[2]; bhi[2 * jj + 1][1] = r[3];
            LDSM4(r, bBase + 2 * APLANE + jj * (16 * ROWB) + kk * 32);
            blo[2 * jj][0] = r[0]; blo[2 * jj + 1][0] = r[1];
            blo[2 * jj][1] = r[2]; blo[2 * jj + 1][1] = r[3];
        }
#pragma unroll
        for (int j = 0; j < 4; j++)
#pragma unroll
            for (int i = 0; i < 2; i++) {
                mma16816_f(A.f[i][j], ahi[i], bhi[j]);
                mma16816_h(A.h[i][j], ahi[i], blo[j]);
                mma16816_h(A.h[i][j], alo[i], bhi[j]);
            }
    }
}

// bias + tanh + split, written straight into the A-tile planar region
__device__ __forceinline__ void epilogue_act(Acc& A, const float* __restrict__ bias,
                                             char* smem, int wm, int wn, int lane) {
    const int r4 = lane >> 2;
    uint32_t* stgH = (uint32_t*)(smem + SM_AHI);
    uint32_t* stgL = (uint32_t*)(smem + SM_ALO);
#pragma unroll
    for (int i = 0; i < 2; i++) {
        int r0 = wm + i * 16 + r4;
#pragma unroll
        for (int j = 0; j < 4; j++) {
            int c0 = wn + j * 8 + (lane & 3) * 2;
            float b0 = bias[c0], b1 = bias[c0 + 1];
            uint32_t hw, lw;
            split2(tanhf(A.f[i][j][0] + b0), tanhf(A.f[i][j][1] + b1), hw, lw);
            stgH[r0 * 68 + (c0 >> 1)] = hw;
            stgL[r0 * 68 + (c0 >> 1)] = lw;
            split2(tanhf(A.f[i][j][2] + b0), tanhf(A.f[i][j][3] + b1), hw, lw);
            stgH[(r0 + 8) * 68 + (c0 >> 1)] = hw;
            stgL[(r0 + 8) * 68 + (c0 >> 1)] = lw;
        }
    }
}

// ---------------- fused 4-layer MLP -------------------------------------------
// grid (M/64, 2): x = m-block, y = net (0 alloc, 1 pay). 256 threads, 2 CTA/SM.
__global__ void __launch_bounds__(256, 2)
fused_mlp(const float* __restrict__ bids, const __half* __restrict__ wt,
          const float* __restrict__ ab0, const float* __restrict__ ab1,
          const float* __restrict__ ab2, const float* __restrict__ ab3,
          const float* __restrict__ pb0, const float* __restrict__ pb1,
          const float* __restrict__ pb2,
          const float* __restrict__ pw3, const float* __restrict__ pb3,
          float* __restrict__ mat, float* __restrict__ frac)
{
    extern __shared__ __align__(16) char smem[];
    const int tid  = threadIdx.x;
    const int lane = tid & 31;
    const int w    = tid >> 5;
    const int wm   = (w & 1) * 32;
    const int wn   = (w >> 1) * 32;
    const int bm   = blockIdx.x * 64;
    const bool pay = blockIdx.y != 0;

    const uint32_t sb = smem_u32(smem);
    const int l15 = lane & 15;
    const int lhi = (lane >> 4) * 16;
    const uint32_t aBase = sb + SM_AHI + (uint32_t)(wm + l15) * ROWB + lhi;
    const uint32_t bBase = sb + SM_BHI + (uint32_t)(wn + l15) * ROWB + lhi;

    const __half* w0h = wt + (pay ? OFF_PW0 : OFF_AW0);
    const __half* w1h = wt + (pay ? OFF_PW1 : OFF_AW1);
    const __half* w2h = wt + (pay ? OFF_PW2 : OFF_AW2);
    const float* b0 = pay ? pb0 : ab0;
    const float* b1 = pay ? pb1 : ab1;
    const float* b2 = pay ? pb2 : ab2;

    Acc acc;

    // ---- L0: K=256 (2 chunks), A from bids f32
    acc.zero();
#pragma unroll 1
    for (int c = 0; c < 2; c++) {
        load_w(sb, w0h, w0h + 32768, 0, c * 128, 256, tid);
        load_f32_pair(smem + SM_AHI, smem + SM_ALO,
                      (const float4*)(bids + (size_t)bm * 256 + c * 128), 64, tid);
        CP_WAIT0(); __syncthreads();
        mma_phase(acc, aBase, bBase);
        __syncthreads();
    }
    load_w(sb, w1h, w1h + 16384, 0, 0, 128, tid);   // prefetch L1 W over epilogue
    acc.merge();
    epilogue_act(acc, b0, smem, wm, wn, lane);
    CP_WAIT0(); __syncthreads();

    // ---- L1
    acc.zero();
    mma_phase(acc, aBase, bBase);
    __syncthreads();
    load_w(sb, w2h, w2h + 16384, 0, 0, 128, tid);   // prefetch L2 W
    acc.merge();
    epilogue_act(acc, b1, smem, wm, wn, lane);
    CP_WAIT0(); __syncthreads();

    // ---- L2
    acc.zero();
    mma_phase(acc, aBase, bBase);
    __syncthreads();
    if (!pay)
        load_w(sb, wt + OFF_AW3, wt + OFF_AW3 + 32768, 0, 0, 128, tid);  // L3 half0
    acc.merge();
    epilogue_act(acc, b2, smem, wm, wn, lane);
    CP_WAIT0(); __syncthreads();

    if (!pay) {
        // ---- L3: N=256 in two halves, f32 -> mat
#pragma unroll 1
        for (int h = 0; h < 2; h++) {
            acc.zero();
            mma_phase(acc, aBase, bBase);
            __syncthreads();
            acc.merge();
            float* stage = (float*)(smem + SM_BHI);   // W consumed; 64x132 f32
            const int r4 = lane >> 2;
#pragma unroll
            for (int i = 0; i < 2; i++) {
                int r0 = wm + i * 16 + r4;
#pragma unroll
                for (int j = 0; j < 4; j++) {
                    int c0 = wn + j * 8 + (lane & 3) * 2;
                    float bb0 = ab3[h * 128 + c0], bb1 = ab3[h * 128 + c0 + 1];
                    stage[r0 * 132 + c0]           = acc.f[i][j][0] + bb0;
                    stage[r0 * 132 + c0 + 1]       = acc.f[i][j][1] + bb1;
                    stage[(r0 + 8) * 132 + c0]     = acc.f[i][j][2] + bb0;
                    stage[(r0 + 8) * 132 + c0 + 1] = acc.f[i][j][3] + bb1;
                }
            }
            __syncthreads();
            float* og = mat + (size_t)bm * 256 + h * 128;
#pragma unroll
            for (int it = 0; it < 32; it++) {
                int lin = it * 256 + tid;
                int row = lin >> 7, col = lin & 127;
                og[row * 256 + col] = stage[row * 132 + col];
            }
            if (h == 0) {
                __syncthreads();   // stage fully read before W overwrite
                load_w(sb, wt + OFF_AW3, wt + OFF_AW3 + 32768, 128, 0, 128, tid);
                CP_WAIT0(); __syncthreads();
            }
        }
    } else {
        // ---- payment head: frac = sigmoid(acts @ pw3 + pb3)
        float* sW = (float*)(smem + SM_BHI);
#pragma unroll
        for (int t = 0; t < 8; t++) sW[t * 256 + tid] = pw3[t * 256 + tid];
        __syncthreads();
        const int s = tid >> 2, q = tid & 3;
        const __half* hh = (const __half*)(smem + SM_AHI) + s * 136;
        const __half* ll = (const __half*)(smem + SM_ALO) + s * 136;
        float a4[4];
#pragma unroll
        for (int j = 0; j < 4; j++) a4[j] = pb3[q * 4 + j];
#pragma unroll 8
        for (int k = 0; k < 128; k++) {
            float av = __half2float(hh[k]) + __half2float(ll[k]);
            const float* wr = sW + k * 16 + q * 4;
#pragma unroll
            for (int j = 0; j < 4; j++) a4[j] = fmaf(av, wr[j], a4[j]);
        }
        float* fo = frac + (size_t)(bm + s) * 16 + q * 4;
#pragma unroll
        for (int j = 0; j < 4; j++)
            fo[j] = __fdividef(1.f, 1.f + __expf(-a4[j]));
    }
}

// ---------------- Sinkhorn: register-resident, 2 threads/sample --------------
__global__ void __launch_bounds__(256) sinkhorn_reg(
    const float* __restrict__ mat, const float* __restrict__ bids,
    const float* __restrict__ frac, float* __restrict__ outA,
    float* __restrict__ outP)
{
    const int tid = threadIdx.x;
    const int p   = tid & 1;
    const int s   = blockIdx.x * 128 + (tid >> 1);
    const float* mrow = mat + (size_t)s * 256 + p * 8;

    float K[16][8];
#pragma unroll
    for (int i = 0; i < 16; i++) {
        float4 x0 = *(const float4*)(mrow + i * 16);
        float4 x1 = *(const float4*)(mrow + i * 16 + 4);
        K[i][0] = __expf(x0.x * 10.f); K[i][1] = __expf(x0.y * 10.f);
        K[i][2] = __expf(x0.z * 10.f); K[i][3] = __expf(x0.w * 10.f);
        K[i][4] = __expf(x1.x * 10.f); K[i][5] = __expf(x1.y * 10.f);
        K[i][6] = __expf(x1.z * 10.f); K[i][7] = __expf(x1.w * 10.f);
    }

    float v[8], v16 = 1.f;
#pragma unroll
    for (int j = 0; j < 8; j++) v[j] = 1.f;
    float u[16], u16;

#pragma unroll 1
    for (int rnd = 0; rnd < 40; rnd++) {
        float r[17];
#pragma unroll
        for (int i = 0; i < 16; i++) {
            float a = K[i][0] * v[0];
#pragma unroll
            for (int j = 1; j < 8; j++) a = fmaf(K[i][j], v[j], a);
            r[i] = a;
        }
        {
            float a = v[0];
#pragma unroll
            for (int j = 1; j < 8; j++) a += v[j];
            r[16] = a;
        }
#pragma unroll
        for (int i = 0; i < 17; i++)
            r[i] += __shfl_xor_sync(0xFFFFFFFFu, r[i], 1);
#pragma unroll
        for (int i = 0; i < 16; i++) u[i] = __fdividef(1.f, r[i] + v16);
        u16 = __fdividef(16.f, r[16] + v16);

        float usum = u[0];
#pragma unroll
        for (int i = 1; i < 16; i++) usum += u[i];
#pragma unroll
        for (int j = 0; j < 8; j++) {
            float c = u16;
#pragma unroll
            for (int i = 0; i < 16; i++) c = fmaf(K[i][j], u[i], c);
            v[j] = __fdividef(1.f, c);
        }
        v16 = __fdividef(16.f, usum + u16);
    }

    const float* brow = bids + (size_t)s * 256 + p * 8;
    float* arow = outA + (size_t)s * 256 + p * 8;
    float pp[16];
#pragma unroll
    for (int i = 0; i < 16; i++) {
        float4 b0 = *(const float4*)(brow + i * 16);
        float4 b1 = *(const float4*)(brow + i * 16 + 4);
        float ui = u[i];
        float a0 = ui * K[i][0] * v[0], a1 = ui * K[i][1] * v[1];
        float a2 = ui * K[i][2] * v[2], a3 = ui * K[i][3] * v[3];
        float a4 = ui * K[i][4] * v[4], a5 = ui * K[i][5] * v[5];
        float a6 = ui * K[i][6] * v[6], a7 = ui * K[i][7] * v[7];
        *(float4*)(arow + i * 16)     = make_float4(a0, a1, a2, a3);
        *(float4*)(arow + i * 16 + 4) = make_float4(a4, a5, a6, a7);
        pp[i] = a0 * b0.x + a1 * b0.y + a2 * b0.z + a3 * b0.w
              + a4 * b1.x + a5 * b1.y + a6 * b1.z + a7 * b1.w;
    }
#pragma unroll
    for (int i = 0; i < 16; i++)
        pp[i] += __shfl_xor_sync(0xFFFFFFFFu, pp[i], 1);

    const float* frow = frac + (size_t)s * 16 + p * 8;
    float4 f0 = *(const float4*)frow;
    float4 f1 = *(const float4*)(frow + 4);
    float pay[8];
#pragma unroll
    for (int q = 0; q < 8; q++) pay[q] = p ? pp[8 + q] : pp[q];
    pay[0] *= f0.x; pay[1] *= f0.y; pay[2] *= f0.z; pay[3] *= f0.w;
    pay[4] *= f1.x; pay[5] *= f1.y; pay[6] *= f1.z; pay[7] *= f1.w;
    float* prow = outP + (size_t)s * 16 + p * 8;
    *(float4*)prow       = make_float4(pay[0], pay[1], pay[2], pay[3]);
    *(float4*)(prow + 4) = make_float4(pay[4], pay[5], pay[6], pay[7]);
}

// ---------------- launch -----------------------------------------------------
extern "C" void kernel_launch(void* const* d_in, const int* in_sizes, int n_in,
                              void* d_out, int out_size)
{
    const float* bids = (const float*)d_in[0];
    const float* aw0 = (const float*)d_in[1];  const float* ab0 = (const float*)d_in[2];
    const float* aw1 = (const float*)d_in[3];  const float* ab1 = (const float*)d_in[4];
    const float* aw2 = (const float*)d_in[5];  const float* ab2 = (const float*)d_in[6];
    const float* aw3 = (const float*)d_in[7];  const float* ab3 = (const float*)d_in[8];
    const float* pw0 = (const float*)d_in[9];  const float* pb0 = (const float*)d_in[10];
    const float* pw1 = (const float*)d_in[11]; const float* pb1 = (const float*)d_in[12];
    const float* pw2 = (const float*)d_in[13]; const float* pb2 = (const float*)d_in[14];
    const float* pw3 = (const float*)d_in[15]; const float* pb3 = (const float*)d_in[16];

    const int M = in_sizes[0] / 256;  // 32768

    void* p;
    cudaGetSymbolAddress(&p, g_mat);  float* mat = (float*)p;
    cudaGetSymbolAddress(&p, g_frac); float* fr  = (float*)p;
    cudaGetSymbolAddress(&p, g_wt);   __half* wt = (__half*)p;

    cudaFuncSetAttribute(fused_mlp, cudaFuncAttributeMaxDynamicSharedMemorySize,
                         SMEM_BYTES);

    pack_w_all<<<dim3(128, 7), 256>>>(aw0, aw1, aw2, aw3, pw0, pw1, pw2, wt);

    fused_mlp<<<dim3(M / 64, 2), 256, SMEM_BYTES>>>(
        bids, wt, ab0, ab1, ab2, ab3, pb0, pb1, pb2, pw3, pb3, mat, fr);

    float* out = (float*)d_out;
    sinkhorn_reg<<<M / 128, 256>>>(mat, bids, fr, out, out + (size_t)M * 256);
}